// round 7
// baseline (speedup 1.0000x reference)
#include <cuda_runtime.h>
#include <cuda_fp16.h>
#include <mma.h>
#include <math.h>
#include <stdint.h>

using namespace nvcuda;

#define B64   64
#define EMB   2048
#define GDIM  4096
#define TENC  64
#define SKV   256
#define NH    32
#define HC    64
#define SPLITS 8

// ---------------- scratch (device globals; no allocation allowed) ----------------
__device__ float g_x1[B64*EMB];
__device__ float g_qkv[B64*EMB];
__device__ float g_attnout[B64*EMB];
__device__ float g_x2[B64*EMB];
__device__ float g_y1[B64*EMB];
__device__ float g_qc[B64*EMB];
__device__ float g_x3[B64*EMB];
__device__ float g_z1[B64*EMB];
__device__ float g_gln[B64*GDIM];
__device__ float g_enck[B64*TENC*EMB];
__device__ float g_encv[B64*TENC*EMB];
__device__ float g_partial[3*SPLITS*B64*GDIM];
__device__ __half g_ench[B64*TENC*EMB];
__device__ __half g_wkh[EMB*EMB];
__device__ __half g_wvh[EMB*EMB];

__device__ __forceinline__ uint2 pack4h(float4 v) {
    __half2 h0 = __floats2half2_rn(v.x, v.y);
    __half2 h1 = __floats2half2_rn(v.z, v.w);
    uint2 u;
    u.x = *(uint32_t*)&h0;
    u.y = *(uint32_t*)&h1;
    return u;
}

// ---------------- fused: attention_state copy + fp16 converts ----------------
__global__ void copy_cvt(const float4* __restrict__ st, float4* __restrict__ std_, long n4,
                         const float4* __restrict__ s0, uint2* __restrict__ d0, long n0,
                         const float4* __restrict__ s1, uint2* __restrict__ d1, long n1,
                         const float4* __restrict__ s2, uint2* __restrict__ d2, long n2) {
    long total = n4 + n0 + n1 + n2;
    for (long i = (long)blockIdx.x * blockDim.x + threadIdx.x; i < total;
         i += (long)gridDim.x * blockDim.x) {
        if (i < n4) std_[i] = st[i];
        else {
            long j = i - n4;
            if (j < n0) d0[j] = pack4h(s0[j]);
            else if (j < n0 + n1) d1[j - n0] = pack4h(s1[j - n0]);
            else d2[j - n0 - n1] = pack4h(s2[j - n0 - n1]);
        }
    }
}

// ---------------- layernorm ----------------
__global__ void ln_kernel(const float* __restrict__ in, const float* __restrict__ g,
                          const float* __restrict__ b, const float* __restrict__ res,
                          float* __restrict__ out, int W) {
    int row = blockIdx.x;
    const float* x = in + (long)row * W;
    float s = 0.f, ss = 0.f;
    for (int i = threadIdx.x; i < W; i += blockDim.x) { float v = x[i]; s += v; ss += v * v; }
    __shared__ float rs[32], rss[32];
    for (int o = 16; o; o >>= 1) { s += __shfl_down_sync(0xffffffffu, s, o); ss += __shfl_down_sync(0xffffffffu, ss, o); }
    int wid = threadIdx.x >> 5, lid = threadIdx.x & 31;
    if (!lid) { rs[wid] = s; rss[wid] = ss; }
    __syncthreads();
    if (threadIdx.x == 0) {
        float S = 0.f, SS = 0.f;
        int nw = blockDim.x >> 5;
        for (int i = 0; i < nw; i++) { S += rs[i]; SS += rss[i]; }
        rs[0] = S; rss[0] = SS;
    }
    __syncthreads();
    float m    = rs[0] / (float)W;
    float var  = rss[0] / (float)W - m * m;
    float rstd = rsqrtf(var + 1e-5f);
    float* o = out + (long)row * W;
    const float* r = res ? res + (long)row * W : nullptr;
    for (int i = threadIdx.x; i < W; i += blockDim.x) {
        float v = (x[i] - m) * rstd * g[i] + b[i];
        o[i] = r ? (r[i] + v) : v;
    }
}

// ---------------- big GEMM: 256x128 tile, 512 threads, fp16 gmem operands ----------
#define BAS_STRIDE 40
#define BBS_STRIDE 136
#define BAS_ELEMS (2 * 256 * BAS_STRIDE)
#define BBS_ELEMS (2 * 32 * BBS_STRIDE)
#define SMEM_BIG ((BAS_ELEMS + BBS_ELEMS) * 2)

__global__ __launch_bounds__(512) void wmma_big_h(
    const __half* __restrict__ A, const __half* __restrict__ W0, const __half* __restrict__ W1,
    float* __restrict__ C0, float* __restrict__ C1, int M, int N, int K) {
    extern __shared__ __half hsm[];
    __half* As = hsm;                   // [2][256][40]
    __half* Bs = hsm + BAS_ELEMS;       // [2][32][136]
    const __half* W = blockIdx.z ? W1 : W0;
    float* C = blockIdx.z ? C1 : C0;
    int m0 = blockIdx.y * 256, n0 = blockIdx.x * 128;
    int tid = threadIdx.x;
    int warp = tid >> 5;
    int wm = warp >> 2;        // 0..3 : 64-row slab
    int wn = warp & 3;         // 0..3 : 32-col slab

    wmma::fragment<wmma::accumulator, 16, 16, 16, float> c[4][2];
    #pragma unroll
    for (int i = 0; i < 4; i++)
        #pragma unroll
        for (int j = 0; j < 2; j++) wmma::fill_fragment(c[i][j], 0.f);

    uint4 ra[2], rb;
    int ar[2], ac[2];
    #pragma unroll
    for (int u = 0; u < 2; u++) {
        int idx = tid + u * 512;                  // A: 256 rows x 4 chunks of 8 halfs
        ar[u] = idx >> 2;  ac[u] = (idx & 3) * 8;
    }
    int br = tid >> 4, bc = (tid & 15) * 8;       // B: 32 rows x 16 chunks

    auto loadG = [&](int kt) {
        #pragma unroll
        for (int u = 0; u < 2; u++)
            ra[u] = *(const uint4*)(A + (long)(m0 + ar[u]) * K + kt + ac[u]);
        rb = *(const uint4*)(W + (long)(kt + br) * N + n0 + bc);
    };
    auto storeS = [&](int buf) {
        #pragma unroll
        for (int u = 0; u < 2; u++)
            *(uint4*)&As[buf * 256 * BAS_STRIDE + ar[u] * BAS_STRIDE + ac[u]] = ra[u];
        *(uint4*)&Bs[buf * 32 * BBS_STRIDE + br * BBS_STRIDE + bc] = rb;
    };

    loadG(0);
    storeS(0);
    __syncthreads();
    int buf = 0;

    for (int kt = 0; kt < K; kt += 32) {
        int nxt = kt + 32;
        if (nxt < K) loadG(nxt);
        const __half* Ab = As + buf * 256 * BAS_STRIDE;
        const __half* Bb = Bs + buf * 32 * BBS_STRIDE;
        #pragma unroll
        for (int k16 = 0; k16 < 32; k16 += 16) {
            wmma::fragment<wmma::matrix_b, 16, 16, 16, __half, wmma::row_major> b[2];
            #pragma unroll
            for (int j = 0; j < 2; j++)
                wmma::load_matrix_sync(b[j], &Bb[k16 * BBS_STRIDE + wn * 32 + j * 16], BBS_STRIDE);
            #pragma unroll
            for (int i = 0; i < 4; i++) {
                wmma::fragment<wmma::matrix_a, 16, 16, 16, __half, wmma::row_major> a;
                wmma::load_matrix_sync(a, &Ab[(wm * 64 + i * 16) * BAS_STRIDE + k16], BAS_STRIDE);
                wmma::mma_sync(c[i][0], a, b[0], c[i][0]);
                wmma::mma_sync(c[i][1], a, b[1], c[i][1]);
            }
        }
        if (nxt < K) storeS(buf ^ 1);
        __syncthreads();
        buf ^= 1;
    }
    #pragma unroll
    for (int i = 0; i < 4; i++)
        #pragma unroll
        for (int j = 0; j < 2; j++)
            wmma::store_matrix_sync(C + (long)(m0 + wm * 64 + i * 16) * N + n0 + wn * 32 + j * 16,
                                    c[i][j], N, wmma::mem_row_major);
}

// ---------------- small GEMM: 64x128 tile, M=64, split-K ----------------
// grid: (N/128, SPLITS, nW). partial[(w*SPLITS+s)*64*N + m*N + n]
__global__ __launch_bounds__(256) void wmma_small(
    const float* __restrict__ A, const float* __restrict__ Wa,
    const float* __restrict__ Wb, const float* __restrict__ Wc,
    float* __restrict__ part, int N, int K) {
    int nt = blockIdx.x, s = blockIdx.y, w = blockIdx.z;
    const float* W = (w == 0) ? Wa : ((w == 1) ? Wb : Wc);
    int Ks = K / SPLITS;
    int k0 = s * Ks;
    int n0 = nt * 128;
    __shared__ __align__(16) __half As[2][64][40];
    __shared__ __align__(16) __half Bs[2][32][136];
    int tid = threadIdx.x;
    int warp = tid >> 5;
    int wm = warp >> 1;        // 0..3 : 16-row slab
    int wn = warp & 1;         // 0..1 : 64-col slab

    wmma::fragment<wmma::accumulator, 16, 16, 16, float> c[4];
    #pragma unroll
    for (int j = 0; j < 4; j++) wmma::fill_fragment(c[j], 0.f);

    float4 ra[2], rb[4];
    int ar[2], ac[2], br[4], bc[4];
    #pragma unroll
    for (int u = 0; u < 2; u++) {
        int idx = tid + u * 256;
        ar[u] = idx >> 3;  ac[u] = (idx & 7) * 4;    // A: 64 rows x 8 float4-cols
    }
    #pragma unroll
    for (int u = 0; u < 4; u++) {
        int idx = tid + u * 256;
        br[u] = idx >> 5;  bc[u] = (idx & 31) * 4;   // B: 32 rows x 32 float4-cols
    }
    auto loadG = [&](int kt) {
        #pragma unroll
        for (int u = 0; u < 2; u++)
            ra[u] = *(const float4*)(A + (long)ar[u] * K + k0 + kt + ac[u]);
        #pragma unroll
        for (int u = 0; u < 4; u++)
            rb[u] = *(const float4*)(W + (long)(k0 + kt + br[u]) * N + n0 + bc[u]);
    };
    auto storeS = [&](int buf) {
        #pragma unroll
        for (int u = 0; u < 2; u++)
            *(uint2*)&As[buf][ar[u]][ac[u]] = pack4h(ra[u]);
        #pragma unroll
        for (int u = 0; u < 4; u++)
            *(uint2*)&Bs[buf][br[u]][bc[u]] = pack4h(rb[u]);
    };

    loadG(0);
    storeS(0);
    __syncthreads();
    int buf = 0;

    for (int kt = 0; kt < Ks; kt += 32) {
        int nxt = kt + 32;
        if (nxt < Ks) loadG(nxt);
        #pragma unroll
        for (int k16 = 0; k16 < 32; k16 += 16) {
            wmma::fragment<wmma::matrix_a, 16, 16, 16, __half, wmma::row_major> a;
            wmma::load_matrix_sync(a, &As[buf][wm * 16][k16], 40);
            #pragma unroll
            for (int j = 0; j < 4; j++) {
                wmma::fragment<wmma::matrix_b, 16, 16, 16, __half, wmma::row_major> b;
                wmma::load_matrix_sync(b, &Bs[buf][k16][wn * 64 + j * 16], 136);
                wmma::mma_sync(c[j], a, b, c[j]);
            }
        }
        if (nxt < Ks) storeS(buf ^ 1);
        __syncthreads();
        buf ^= 1;
    }
    float* P = part + (long)(w * SPLITS + s) * 64 * N;
    #pragma unroll
    for (int j = 0; j < 4; j++)
        wmma::store_matrix_sync(P + (long)(wm * 16) * N + n0 + wn * 64 + j * 16,
                                c[j], N, wmma::mem_row_major);
}

// ---------------- fused epilogues ----------------
__global__ void reduce_qkv_scatter(const float* __restrict__ part, float* __restrict__ q,
                                   float* __restrict__ outstate, const int* __restrict__ tokp) {
    int tok = *tokp;
    int idx = blockIdx.x * blockDim.x + threadIdx.x;
    if (idx >= 3 * B64 * EMB) return;
    int w = idx / (B64 * EMB);
    int rem = idx - w * B64 * EMB;
    float s = 0.f;
    #pragma unroll
    for (int k = 0; k < SPLITS; k++) s += part[(long)(w * SPLITS + k) * B64 * EMB + rem];
    if (w == 0) {
        q[rem] = s;
    } else {
        int b = rem >> 11, e = rem & (EMB - 1);
        long dst = ((long)((w == 1 ? 0 : B64) + b) * SKV + tok) * EMB + e;
        outstate[dst] = s;
    }
}

// reduce + LN1(+res) -> xout; LN2(xout) -> yout. one block per row, W=EMB
__global__ void reduce_ln_ln(const float* __restrict__ part,
                             const float* __restrict__ g1, const float* __restrict__ b1,
                             const float* __restrict__ res,
                             const float* __restrict__ g2, const float* __restrict__ b2,
                             float* __restrict__ xout, float* __restrict__ yout) {
    const int W = EMB;
    __shared__ float buf[EMB];
    __shared__ float rs[32], rss[32];
    int row = blockIdx.x;
    float s = 0.f, ss = 0.f;
    for (int i = threadIdx.x; i < W; i += blockDim.x) {
        float v = 0.f;
        #pragma unroll
        for (int k = 0; k < SPLITS; k++) v += part[(long)k * B64 * W + (long)row * W + i];
        buf[i] = v; s += v; ss += v * v;
    }
    int wid = threadIdx.x >> 5, lid = threadIdx.x & 31;
    for (int o = 16; o; o >>= 1) { s += __shfl_down_sync(0xffffffffu, s, o); ss += __shfl_down_sync(0xffffffffu, ss, o); }
    if (!lid) { rs[wid] = s; rss[wid] = ss; }
    __syncthreads();
    if (threadIdx.x == 0) {
        float S = 0.f, SS = 0.f;
        for (int i = 0; i < (int)(blockDim.x >> 5); i++) { S += rs[i]; SS += rss[i]; }
        rs[0] = S; rss[0] = SS;
    }
    __syncthreads();
    float m    = rs[0] / (float)W;
    float var  = rss[0] / (float)W - m * m;
    float rstd = rsqrtf(var + 1e-5f);
    __syncthreads();
    // pass 2: x = res + LN1(buf); accumulate stats of x
    float s2 = 0.f, ss2 = 0.f;
    const float* r = res + (long)row * W;
    float* xo = xout + (long)row * W;
    for (int i = threadIdx.x; i < W; i += blockDim.x) {
        float t = r[i] + (buf[i] - m) * rstd * g1[i] + b1[i];
        buf[i] = t; xo[i] = t; s2 += t; ss2 += t * t;
    }
    for (int o = 16; o; o >>= 1) { s2 += __shfl_down_sync(0xffffffffu, s2, o); ss2 += __shfl_down_sync(0xffffffffu, ss2, o); }
    if (!lid) { rs[wid] = s2; rss[wid] = ss2; }
    __syncthreads();
    if (threadIdx.x == 0) {
        float S = 0.f, SS = 0.f;
        for (int i = 0; i < (int)(blockDim.x >> 5); i++) { S += rs[i]; SS += rss[i]; }
        rs[0] = S; rss[0] = SS;
    }
    __syncthreads();
    float m2    = rs[0] / (float)W;
    float var2  = rss[0] / (float)W - m2 * m2;
    float rstd2 = rsqrtf(var2 + 1e-5f);
    float* yo = yout + (long)row * W;
    for (int i = threadIdx.x; i < W; i += blockDim.x)
        yo[i] = (buf[i] - m2) * rstd2 * g2[i] + b2[i];
}

// reduce fc0/fc1 + gelu*mul + LN -> out. one block per row, W=GDIM
__global__ void reduce_gelu_ln(const float* __restrict__ part,
                               const float* __restrict__ g, const float* __restrict__ b,
                               float* __restrict__ out) {
    const int W = GDIM;
    __shared__ float buf[GDIM];
    __shared__ float rs[32], rss[32];
    int row = blockIdx.x;
    float s = 0.f, ss = 0.f;
    for (int i = threadIdx.x; i < W; i += blockDim.x) {
        float a = 0.f, c = 0.f;
        #pragma unroll
        for (int k = 0; k < SPLITS; k++) {
            a += part[(long)k * B64 * W + (long)row * W + i];
            c += part[(long)(SPLITS + k) * B64 * W + (long)row * W + i];
        }
        float gl = 0.5f * a * (1.f + erff(a * 0.70710678118654752f));
        float v = gl * c;
        buf[i] = v; s += v; ss += v * v;
    }
    int wid = threadIdx.x >> 5, lid = threadIdx.x & 31;
    for (int o = 16; o; o >>= 1) { s += __shfl_down_sync(0xffffffffu, s, o); ss += __shfl_down_sync(0xffffffffu, ss, o); }
    if (!lid) { rs[wid] = s; rss[wid] = ss; }
    __syncthreads();
    if (threadIdx.x == 0) {
        float S = 0.f, SS = 0.f;
        for (int i = 0; i < (int)(blockDim.x >> 5); i++) { S += rs[i]; SS += rss[i]; }
        rs[0] = S; rss[0] = SS;
    }
    __syncthreads();
    float m    = rs[0] / (float)W;
    float var  = rss[0] / (float)W - m * m;
    float rstd = rsqrtf(var + 1e-5f);
    float* o = out + (long)row * W;
    for (int i = threadIdx.x; i < W; i += blockDim.x)
        o[i] = (buf[i] - m) * rstd * g[i] + b[i];
}

__global__ void reduce_add(const float* __restrict__ part, const float* __restrict__ res,
                           float* __restrict__ o) {
    int i = blockIdx.x * blockDim.x + threadIdx.x;
    if (i >= B64 * EMB) return;
    float s = 0.f;
    #pragma unroll
    for (int k = 0; k < SPLITS; k++) s += part[(long)k * B64 * EMB + i];
    o[i] = res[i] + s;
}

__global__ void reduce_one(const float* __restrict__ part, float* __restrict__ o, long WN) {
    for (long i = (long)blockIdx.x * blockDim.x + threadIdx.x; i < WN;
         i += (long)gridDim.x * blockDim.x) {
        float s = 0.f;
        #pragma unroll
        for (int k = 0; k < SPLITS; k++) s += part[(long)k * WN + i];
        o[i] = s;
    }
}

// ---------------- attention (one block per (b,h)) ----------------
__global__ void attn_kernel(const float* __restrict__ Q, const float* __restrict__ Kv,
                            const float* __restrict__ Vv, float* __restrict__ O,
                            int Srow, int Lfixed, const int* __restrict__ tokp) {
    int b = blockIdx.x, h = blockIdx.y;
    int L = tokp ? (*tokp + 1) : Lfixed;
    __shared__ float qsh[HC];
    __shared__ float sc[SKV];
    __shared__ float red[128];
    int tid = threadIdx.x;
    if (tid < HC) qsh[tid] = Q[(long)b * EMB + h * HC + tid];
    __syncthreads();

    int warp = tid >> 5, lane = tid & 31;
    for (int j = warp; j < L; j += 4) {
        const float* kp = Kv + ((long)b * Srow + j) * EMB + h * HC;
        float d = qsh[lane] * kp[lane] + qsh[lane + 32] * kp[lane + 32];
        for (int o = 16; o; o >>= 1) d += __shfl_down_sync(0xffffffffu, d, o);
        if (!lane) sc[j] = d * 0.125f;
    }
    __syncthreads();

    float mx = -1e30f;
    for (int j = tid; j < L; j += 128) mx = fmaxf(mx, sc[j]);
    red[tid] = mx; __syncthreads();
    for (int st = 64; st; st >>= 1) { if (tid < st) red[tid] = fmaxf(red[tid], red[tid + st]); __syncthreads(); }
    mx = red[0];
    __syncthreads();

    float sum = 0.f;
    for (int j = tid; j < L; j += 128) { float e = expf(sc[j] - mx); sc[j] = e; sum += e; }
    red[tid] = sum; __syncthreads();
    for (int st = 64; st; st >>= 1) { if (tid < st) red[tid] += red[tid + st]; __syncthreads(); }
    float inv = 1.f / red[0];

    if (tid < HC) {
        float acc = 0.f;
        const float* vb = Vv + (long)b * Srow * EMB + h * HC + tid;
        for (int j = 0; j < L; j++) acc += sc[j] * vb[(long)j * EMB];
        O[(long)b * EMB + h * HC + tid] = acc * inv;
    }
}

// ---------------- host orchestration ----------------
extern "C" void kernel_launch(void* const* d_in, const int* in_sizes, int n_in,
                              void* d_out, int out_size) {
    const float* dec        = (const float*)d_in[0];
    const float* enc        = (const float*)d_in[1];
    const float* astate     = (const float*)d_in[2];
    const int*   tokp       = (const int*)d_in[4];
    const float* ln_pre_sa_g = (const float*)d_in[5];
    const float* ln_pre_sa_b = (const float*)d_in[6];
    const float* ln_sa_g     = (const float*)d_in[7];
    const float* ln_sa_b     = (const float*)d_in[8];
    const float* ln_pre_ca_g = (const float*)d_in[9];
    const float* ln_pre_ca_b = (const float*)d_in[10];
    const float* ln_ca_g     = (const float*)d_in[11];
    const float* ln_ca_b     = (const float*)d_in[12];
    const float* sa_wq = (const float*)d_in[13];
    const float* sa_wk = (const float*)d_in[14];
    const float* sa_wv = (const float*)d_in[15];
    const float* sa_wo = (const float*)d_in[16];
    const float* ca_wq = (const float*)d_in[17];
    const float* ca_wk = (const float*)d_in[18];
    const float* ca_wv = (const float*)d_in[19];
    const float* ca_wo = (const float*)d_in[20];
    const float* glu_ln0_g = (const float*)d_in[21];
    const float* glu_ln0_b = (const float*)d_in[22];
    const float* glu_fc0   = (const float*)d_in[23];
    const float* glu_fc1   = (const float*)d_in[24];
    const float* glu_ln1_g = (const float*)d_in[25];
    const float* glu_ln1_b = (const float*)d_in[26];
    const float* glu_fc2   = (const float*)d_in[27];

    float* out       = (float*)d_out;
    float* out_x     = out;
    float* out_state = out + (long)B64 * EMB;

    float *x1, *qkv, *attnout, *x2, *y1, *qc, *x3, *z1, *gln, *enck, *encv, *part;
    __half *ench, *wkh, *wvh;
    cudaGetSymbolAddress((void**)&x1, g_x1);
    cudaGetSymbolAddress((void**)&qkv, g_qkv);
    cudaGetSymbolAddress((void**)&attnout, g_attnout);
    cudaGetSymbolAddress((void**)&x2, g_x2);
    cudaGetSymbolAddress((void**)&y1, g_y1);
    cudaGetSymbolAddress((void**)&qc, g_qc);
    cudaGetSymbolAddress((void**)&x3, g_x3);
    cudaGetSymbolAddress((void**)&z1, g_z1);
    cudaGetSymbolAddress((void**)&gln, g_gln);
    cudaGetSymbolAddress((void**)&enck, g_enck);
    cudaGetSymbolAddress((void**)&encv, g_encv);
    cudaGetSymbolAddress((void**)&part, g_partial);
    cudaGetSymbolAddress((void**)&ench, g_ench);
    cudaGetSymbolAddress((void**)&wkh, g_wkh);
    cudaGetSymbolAddress((void**)&wvh, g_wvh);

    cudaFuncSetAttribute(wmma_big_h, cudaFuncAttributeMaxDynamicSharedMemorySize, SMEM_BIG);

    // 0. fused: state copy + fp16 converts (enc, ca_wk, ca_wv)
    long n4 = (long)2 * B64 * SKV * EMB / 4;
    long ne = (long)B64 * TENC * EMB / 4, nw = (long)EMB * EMB / 4;
    copy_cvt<<<4096, 256>>>((const float4*)astate, (float4*)out_state, n4,
                            (const float4*)enc, (uint2*)ench, ne,
                            (const float4*)ca_wk, (uint2*)wkh, nw,
                            (const float4*)ca_wv, (uint2*)wvh, nw);

    // 1. x1 = LN(decoder_state)
    ln_kernel<<<B64, 256>>>(dec, ln_pre_sa_g, ln_pre_sa_b, nullptr, x1, EMB);

    // 2. q/k/v projections
    wmma_small<<<dim3(EMB / 128, SPLITS, 3), 256>>>(x1, sa_wq, sa_wk, sa_wv, part, EMB, EMB);

    // 3. fused reduce + scatter into cache
    reduce_qkv_scatter<<<(3 * B64 * EMB) / 256, 256>>>(part, qkv, out_state, tokp);

    // 4. big cross-attn K/V projection (256x128 tiles, fp16 operands)
    wmma_big_h<<<dim3(EMB / 128, (B64 * TENC) / 256, 2), 512, SMEM_BIG>>>(
        ench, wkh, wvh, enck, encv, B64 * TENC, EMB, EMB);

    // 5. self-attention over updated cache
    attn_kernel<<<dim3(B64, NH), 128>>>(qkv, out_state, out_state + (long)B64 * SKV * EMB,
                                        attnout, SKV, 0, tokp);

    // 6. sa out-proj -> fused reduce+LN+res (x2) + LN_pre_ca (y1)
    wmma_small<<<dim3(EMB / 128, SPLITS, 1), 256>>>(attnout, sa_wo, sa_wo, sa_wo, part, EMB, EMB);
    reduce_ln_ln<<<B64, 256>>>(part, ln_sa_g, ln_sa_b, dec, ln_pre_ca_g, ln_pre_ca_b, x2, y1);

    // 7. cross-attention
    wmma_small<<<dim3(EMB / 128, SPLITS, 1), 256>>>(y1, ca_wq, ca_wq, ca_wq, part, EMB, EMB);
    reduce_one<<<512, 256>>>(part, qc, (long)B64 * EMB);
    attn_kernel<<<dim3(B64, NH), 128>>>(qc, enck, encv, attnout, TENC, TENC, nullptr);
    wmma_small<<<dim3(EMB / 128, SPLITS, 1), 256>>>(attnout, ca_wo, ca_wo, ca_wo, part, EMB, EMB);
    reduce_ln_ln<<<B64, 256>>>(part, ln_ca_g, ln_ca_b, x2, glu_ln0_g, glu_ln0_b, x3, z1);

    // 8. GLU block
    wmma_small<<<dim3(GDIM / 128, SPLITS, 2), 256>>>(z1, glu_fc0, glu_fc1, glu_fc1, part, GDIM, EMB);
    reduce_gelu_ln<<<B64, 256>>>(part, glu_ln1_g, glu_ln1_b, gln);
    wmma_small<<<dim3(EMB / 128, SPLITS, 1), 256>>>(gln, glu_fc2, glu_fc2, glu_fc2, part, EMB, GDIM);
    reduce_add<<<512, 256>>>(part, x3, out_x);
}

// round 11
// speedup vs baseline: 1.1755x; 1.1755x over previous
#include <cuda_runtime.h>
#include <cuda_fp16.h>
#include <mma.h>
#include <math.h>
#include <stdint.h>

using namespace nvcuda;

#define B64   64
#define EMB   2048
#define GDIM  4096
#define TENC  64
#define SKV   256
#define NH    32
#define HC    64
#define SPLITS 8

// ---------------- scratch (device globals; no allocation allowed) ----------------
__device__ float g_x1[B64*EMB];
__device__ float g_qkv[B64*EMB];
__device__ float g_attnout[B64*EMB];
__device__ float g_x2[B64*EMB];
__device__ float g_y1[B64*EMB];
__device__ float g_qc[B64*EMB];
__device__ float g_x3[B64*EMB];
__device__ float g_z1[B64*EMB];
__device__ float g_gln[B64*GDIM];
__device__ float g_partial[3*SPLITS*B64*GDIM];
__device__ float g_vpart[NH*4*HC*B64];
__device__ __half g_ench[B64*TENC*EMB];
__device__ __half g_qk[B64*NH*EMB];
__device__ __half g_ctx[B64*NH*EMB];

__device__ __forceinline__ uint2 pack4h(float4 v) {
    __half2 h0 = __floats2half2_rn(v.x, v.y);
    __half2 h1 = __floats2half2_rn(v.z, v.w);
    uint2 u;
    u.x = *(uint32_t*)&h0;
    u.y = *(uint32_t*)&h1;
    return u;
}

// ---------------- fused: attention_state copy + enc fp16 convert ----------------
__global__ void copy_cvt(const float4* __restrict__ st, float4* __restrict__ std_, long n4,
                         const float4* __restrict__ s0, uint2* __restrict__ d0, long n0) {
    long total = n4 + n0;
    for (long i = (long)blockIdx.x * blockDim.x + threadIdx.x; i < total;
         i += (long)gridDim.x * blockDim.x) {
        if (i < n4) std_[i] = st[i];
        else d0[i - n4] = pack4h(s0[i - n4]);
    }
}

// ---------------- layernorm ----------------
__global__ void ln_kernel(const float* __restrict__ in, const float* __restrict__ g,
                          const float* __restrict__ b, const float* __restrict__ res,
                          float* __restrict__ out, int W) {
    int row = blockIdx.x;
    const float* x = in + (long)row * W;
    float s = 0.f, ss = 0.f;
    for (int i = threadIdx.x; i < W; i += blockDim.x) { float v = x[i]; s += v; ss += v * v; }
    __shared__ float rs[32], rss[32];
    for (int o = 16; o; o >>= 1) { s += __shfl_down_sync(0xffffffffu, s, o); ss += __shfl_down_sync(0xffffffffu, ss, o); }
    int wid = threadIdx.x >> 5, lid = threadIdx.x & 31;
    if (!lid) { rs[wid] = s; rss[wid] = ss; }
    __syncthreads();
    if (threadIdx.x == 0) {
        float S = 0.f, SS = 0.f;
        int nw = blockDim.x >> 5;
        for (int i = 0; i < nw; i++) { S += rs[i]; SS += rss[i]; }
        rs[0] = S; rss[0] = SS;
    }
    __syncthreads();
    float m    = rs[0] / (float)W;
    float var  = rss[0] / (float)W - m * m;
    float rstd = rsqrtf(var + 1e-5f);
    float* o = out + (long)row * W;
    const float* r = res ? res + (long)row * W : nullptr;
    for (int i = threadIdx.x; i < W; i += blockDim.x) {
        float v = (x[i] - m) * rstd * g[i] + b[i];
        o[i] = r ? (r[i] + v) : v;
    }
}

// ---------------- small GEMM: 64x128 tile, M=64, split-K ----------------
__global__ __launch_bounds__(256) void wmma_small(
    const float* __restrict__ A, const float* __restrict__ Wa,
    const float* __restrict__ Wb, const float* __restrict__ Wc,
    float* __restrict__ part, int N, int K) {
    int nt = blockIdx.x, s = blockIdx.y, w = blockIdx.z;
    const float* W = (w == 0) ? Wa : ((w == 1) ? Wb : Wc);
    int Ks = K / SPLITS;
    int k0 = s * Ks;
    int n0 = nt * 128;
    __shared__ __align__(16) __half As[2][64][40];
    __shared__ __align__(16) __half Bs[2][32][136];
    int tid = threadIdx.x;
    int warp = tid >> 5;
    int wm = warp >> 1;
    int wn = warp & 1;

    wmma::fragment<wmma::accumulator, 16, 16, 16, float> c[4];
    #pragma unroll
    for (int j = 0; j < 4; j++) wmma::fill_fragment(c[j], 0.f);

    float4 ra[2], rb[4];
    int ar[2], ac[2], br[4], bc[4];
    #pragma unroll
    for (int u = 0; u < 2; u++) {
        int idx = tid + u * 256;
        ar[u] = idx >> 3;  ac[u] = (idx & 7) * 4;
    }
    #pragma unroll
    for (int u = 0; u < 4; u++) {
        int idx = tid + u * 256;
        br[u] = idx >> 5;  bc[u] = (idx & 31) * 4;
    }
    auto loadG = [&](int kt) {
        #pragma unroll
        for (int u = 0; u < 2; u++)
            ra[u] = *(const float4*)(A + (long)ar[u] * K + k0 + kt + ac[u]);
        #pragma unroll
        for (int u = 0; u < 4; u++)
            rb[u] = *(const float4*)(W + (long)(k0 + kt + br[u]) * N + n0 + bc[u]);
    };
    auto storeS = [&](int buf) {
        #pragma unroll
        for (int u = 0; u < 2; u++)
            *(uint2*)&As[buf][ar[u]][ac[u]] = pack4h(ra[u]);
        #pragma unroll
        for (int u = 0; u < 4; u++)
            *(uint2*)&Bs[buf][br[u]][bc[u]] = pack4h(rb[u]);
    };

    loadG(0);
    storeS(0);
    __syncthreads();
    int buf = 0;

    for (int kt = 0; kt < Ks; kt += 32) {
        int nxt = kt + 32;
        if (nxt < Ks) loadG(nxt);
        #pragma unroll
        for (int k16 = 0; k16 < 32; k16 += 16) {
            wmma::fragment<wmma::matrix_a, 16, 16, 16, __half, wmma::row_major> a;
            wmma::load_matrix_sync(a, &As[buf][wm * 16][k16], 40);
            #pragma unroll
            for (int j = 0; j < 4; j++) {
                wmma::fragment<wmma::matrix_b, 16, 16, 16, __half, wmma::row_major> b;
                wmma::load_matrix_sync(b, &Bs[buf][k16][wn * 64 + j * 16], 136);
                wmma::mma_sync(c[j], a, b, c[j]);
            }
        }
        if (nxt < Ks) storeS(buf ^ 1);
        __syncthreads();
        buf ^= 1;
    }
    float* P = part + (long)(w * SPLITS + s) * 64 * N;
    #pragma unroll
    for (int j = 0; j < 4; j++)
        wmma::store_matrix_sync(P + (long)(wm * 16) * N + n0 + wn * 64 + j * 16,
                                c[j], N, wmma::mem_row_major);
}

// ---------------- qk_gemm: qk[b,h,e] = sum_c qc[b,h*64+c] * Wk[e,h*64+c] ------------
// grid (16 e-tiles, 32 h), 256 threads. output fp16 qk[(b*32+h)*2048 + e]
__global__ __launch_bounds__(256) void qk_gemm(const float* __restrict__ qc,
                                               const float* __restrict__ Wk,
                                               __half* __restrict__ qk) {
    int e0 = blockIdx.x * 128, h = blockIdx.y;
    __shared__ __align__(16) __half As[64][72];    // [b][c]
    __shared__ __align__(16) __half Bs[128][72];   // [e][c]  (B col-major view)
    __shared__ float patch[8][16][20];
    int tid = threadIdx.x;
    int warp = tid >> 5, lane = tid & 31;
    int wm = warp >> 1;   // 4 x 16 b-rows
    int wn = warp & 1;    // 2 x 64 e-cols

    #pragma unroll
    for (int u = 0; u < 4; u++) {
        int idx = tid + u * 256;           // 1024 float4 over 64x64
        int b = idx >> 4, c4 = (idx & 15) * 4;
        float4 v = *(const float4*)(qc + (long)b * EMB + h * 64 + c4);
        *(uint2*)&As[b][c4] = pack4h(v);
    }
    #pragma unroll
    for (int u = 0; u < 8; u++) {
        int idx = tid + u * 256;           // 2048 float4 over 128x64
        int e = idx >> 4, c4 = (idx & 15) * 4;
        float4 v = *(const float4*)(Wk + (long)(e0 + e) * EMB + h * 64 + c4);
        *(uint2*)&Bs[e][c4] = pack4h(v);
    }
    __syncthreads();

    wmma::fragment<wmma::accumulator, 16, 16, 16, float> c[4];
    #pragma unroll
    for (int j = 0; j < 4; j++) wmma::fill_fragment(c[j], 0.f);
    #pragma unroll
    for (int k16 = 0; k16 < 64; k16 += 16) {
        wmma::fragment<wmma::matrix_a, 16, 16, 16, __half, wmma::row_major> a;
        wmma::load_matrix_sync(a, &As[wm * 16][k16], 72);
        #pragma unroll
        for (int j = 0; j < 4; j++) {
            wmma::fragment<wmma::matrix_b, 16, 16, 16, __half, wmma::col_major> b;
            wmma::load_matrix_sync(b, &Bs[wn * 64 + j * 16][k16], 72);
            wmma::mma_sync(c[j], a, b, c[j]);
        }
    }
    // bounce to fp16 global
    #pragma unroll
    for (int j = 0; j < 4; j++) {
        wmma::store_matrix_sync(&patch[warp][0][0], c[j], 20, wmma::mem_row_major);
        __syncwarp();
        int r = lane >> 1, c0 = (lane & 1) * 8;
        float* p = &patch[warp][r][c0];
        __half2 h0 = __floats2half2_rn(p[0], p[1]);
        __half2 h1 = __floats2half2_rn(p[2], p[3]);
        __half2 h2 = __floats2half2_rn(p[4], p[5]);
        __half2 h3 = __floats2half2_rn(p[6], p[7]);
        uint4 pk = make_uint4(*(uint32_t*)&h0, *(uint32_t*)&h1, *(uint32_t*)&h2, *(uint32_t*)&h3);
        int b = wm * 16 + r;
        long off = ((long)b * NH + h) * EMB + e0 + wn * 64 + j * 16 + c0;
        *(uint4*)(qk + off) = pk;
        __syncwarp();
    }
}

// ---------------- cross_attn: scores + softmax + ctx, one block per batch ----------
// scores[h,k] = 0.125 * qk[b,h,:]·ench[b,k,:]; w = softmax_k; ctx[b,h,:] = w·ench[b]
__global__ __launch_bounds__(256) void cross_attn(const __half* __restrict__ qk,
                                                  const __half* __restrict__ ench,
                                                  __half* __restrict__ ctx) {
    int b = blockIdx.x;
    int tid = threadIdx.x;
    int warp = tid >> 5, lane = tid & 31;
    const __half* A = qk + (long)b * NH * EMB;       // [32h x 2048] row-major
    const __half* E = ench + (long)b * TENC * EMB;   // [64k x 2048] row-major
    __shared__ float sc[32][72];
    __shared__ __half wsh[32][72];
    __shared__ float patch[8][16][20];

    // scores: [32 x 64] = A[32x2048] @ E^T ; warps: wm(2) x wn(4)
    {
        int wm = warp >> 2, wn = warp & 3;
        wmma::fragment<wmma::accumulator, 16, 16, 16, float> acc;
        wmma::fill_fragment(acc, 0.f);
        for (int k16 = 0; k16 < EMB; k16 += 16) {
            wmma::fragment<wmma::matrix_a, 16, 16, 16, __half, wmma::row_major> a;
            wmma::fragment<wmma::matrix_b, 16, 16, 16, __half, wmma::col_major> bb;
            wmma::load_matrix_sync(a, A + (long)(wm * 16) * EMB + k16, EMB);
            wmma::load_matrix_sync(bb, E + (long)(wn * 16) * EMB + k16, EMB);
            wmma::mma_sync(acc, a, bb, acc);
        }
        wmma::store_matrix_sync(&sc[wm * 16][wn * 16], acc, 72, wmma::mem_row_major);
    }
    __syncthreads();

    // softmax rows (h): 32 threads, one row each
    if (tid < 32) {
        float mx = -1e30f;
        #pragma unroll
        for (int k = 0; k < TENC; k++) mx = fmaxf(mx, sc[tid][k] * 0.125f);
        float sum = 0.f;
        float ex[TENC];
        #pragma unroll
        for (int k = 0; k < TENC; k++) { ex[k] = expf(sc[tid][k] * 0.125f - mx); sum += ex[k]; }
        float inv = 1.f / sum;
        #pragma unroll
        for (int k = 0; k < TENC; k++) wsh[tid][k] = __float2half(ex[k] * inv);
    }
    __syncthreads();

    // ctx: [32 x 2048] = wsh[32x64] @ E[64x2048]; warps: wm(2) x strip wn(4 of 128 n-tiles)
    {
        int wm = warp >> 2, wn = warp & 3;
        for (int nt = wn; nt < 128; nt += 4) {
            wmma::fragment<wmma::accumulator, 16, 16, 16, float> acc;
            wmma::fill_fragment(acc, 0.f);
            #pragma unroll
            for (int kk = 0; kk < TENC; kk += 16) {
                wmma::fragment<wmma::matrix_a, 16, 16, 16, __half, wmma::row_major> a;
                wmma::fragment<wmma::matrix_b, 16, 16, 16, __half, wmma::row_major> bb;
                wmma::load_matrix_sync(a, &wsh[wm * 16][kk], 72);
                wmma::load_matrix_sync(bb, E + (long)kk * EMB + nt * 16, EMB);
                wmma::mma_sync(acc, a, bb, acc);
            }
            wmma::store_matrix_sync(&patch[warp][0][0], acc, 20, wmma::mem_row_major);
            __syncwarp();
            int r = lane >> 1, c0 = (lane & 1) * 8;
            float* p = &patch[warp][r][c0];
            __half2 h0 = __floats2half2_rn(p[0], p[1]);
            __half2 h1 = __floats2half2_rn(p[2], p[3]);
            __half2 h2 = __floats2half2_rn(p[4], p[5]);
            __half2 h3 = __floats2half2_rn(p[6], p[7]);
            uint4 pk = make_uint4(*(uint32_t*)&h0, *(uint32_t*)&h1, *(uint32_t*)&h2, *(uint32_t*)&h3);
            int h = wm * 16 + r;
            long off = ((long)b * NH + h) * EMB + nt * 16 + c0;
            *(uint4*)(ctx + off) = pk;
            __syncwarp();
        }
    }
}

// ---------------- outv_gemm: out[b,h*64+c] = sum_e ctx[b,h,e] * Wv[e,h*64+c] -------
// grid (32 h, 4 splits), 256 threads. partial [h][s][b(64) x c(64)]
__global__ __launch_bounds__(256) void outv_gemm(const __half* __restrict__ ctx,
                                                 const float* __restrict__ Wv,
                                                 float* __restrict__ part) {
    int h = blockIdx.x, s = blockIdx.y;
    int k0 = s * 512;
    __shared__ __align__(16) __half Bs[32][72];
    int tid = threadIdx.x;
    int warp = tid >> 5;
    int wm = warp >> 1;   // 4 x 16 b-rows
    int wn = warp & 1;    // 2 x 32 c-cols
    const __half* A = ctx + (long)h * EMB + k0;   // row b at + b*65536

    wmma::fragment<wmma::accumulator, 16, 16, 16, float> c[2];
    wmma::fill_fragment(c[0], 0.f);
    wmma::fill_fragment(c[1], 0.f);

    for (int kt = 0; kt < 512; kt += 32) {
        #pragma unroll
        for (int u = 0; u < 2; u++) {
            int idx = tid + u * 256;          // 512 float4 over 32x64
            int e = idx >> 4, c4 = (idx & 15) * 4;
            float4 v = *(const float4*)(Wv + (long)(k0 + kt + e) * EMB + h * 64 + c4);
            *(uint2*)&Bs[e][c4] = pack4h(v);
        }
        __syncthreads();
        #pragma unroll
        for (int k16 = 0; k16 < 32; k16 += 16) {
            wmma::fragment<wmma::matrix_a, 16, 16, 16, __half, wmma::row_major> a;
            wmma::load_matrix_sync(a, A + (long)(wm * 16) * (NH * EMB) + kt + k16, NH * EMB);
            #pragma unroll
            for (int j = 0; j < 2; j++) {
                wmma::fragment<wmma::matrix_b, 16, 16, 16, __half, wmma::row_major> bb;
                wmma::load_matrix_sync(bb, &Bs[k16][wn * 32 + j * 16], 72);
                wmma::mma_sync(c[j], a, bb, c[j]);
            }
        }
        __syncthreads();
    }
    float* P = part + (long)(h * 4 + s) * 4096;
    #pragma unroll
    for (int j = 0; j < 2; j++)
        wmma::store_matrix_sync(P + (long)(wm * 16) * 64 + wn * 32 + j * 16,
                                c[j], 64, wmma::mem_row_major);
}

__global__ void reduce_outv(const float* __restrict__ part, float* __restrict__ attnout) {
    int idx = blockIdx.x * blockDim.x + threadIdx.x;
    if (idx >= B64 * EMB) return;
    int b = idx >> 11, r = idx & (EMB - 1);
    int h = r >> 6, cc = r & 63;
    float s = 0.f;
    #pragma unroll
    for (int k = 0; k < 4; k++) s += part[(long)(h * 4 + k) * 4096 + b * 64 + cc];
    attnout[idx] = s;
}

// ---------------- fused epilogues ----------------
__global__ void reduce_qkv_scatter(const float* __restrict__ part, float* __restrict__ q,
                                   float* __restrict__ outstate, const int* __restrict__ tokp) {
    int tok = *tokp;
    int idx = blockIdx.x * blockDim.x + threadIdx.x;
    if (idx >= 3 * B64 * EMB) return;
    int w = idx / (B64 * EMB);
    int rem = idx - w * B64 * EMB;
    float s = 0.f;
    #pragma unroll
    for (int k = 0; k < SPLITS; k++) s += part[(long)(w * SPLITS + k) * B64 * EMB + rem];
    if (w == 0) {
        q[rem] = s;
    } else {
        int b = rem >> 11, e = rem & (EMB - 1);
        long dst = ((long)((w == 1 ? 0 : B64) + b) * SKV + tok) * EMB + e;
        outstate[dst] = s;
    }
}

__global__ void reduce_ln_ln(const float* __restrict__ part,
                             const float* __restrict__ g1, const float* __restrict__ b1,
                             const float* __restrict__ res,
                             const float* __restrict__ g2, const float* __restrict__ b2,
                             float* __restrict__ xout, float* __restrict__ yout) {
    const int W = EMB;
    __shared__ float buf[EMB];
    __shared__ float rs[32], rss[32];
    int row = blockIdx.x;
    float s = 0.f, ss = 0.f;
    for (int i = threadIdx.x; i < W; i += blockDim.x) {
        float v = 0.f;
        #pragma unroll
        for (int k = 0; k < SPLITS; k++) v += part[(long)k * B64 * W + (long)row * W + i];
        buf[i] = v; s += v; ss += v * v;
    }
    int wid = threadIdx.x >> 5, lid = threadIdx.x & 31;
    for (int o = 16; o; o >>= 1) { s += __shfl_down_sync(0xffffffffu, s, o); ss += __shfl_down_sync(0xffffffffu, ss, o); }
    if (!lid) { rs[wid] = s; rss[wid] = ss; }
    __syncthreads();
    if (threadIdx.x == 0) {
        float S = 0.f, SS = 0.f;
        for (int i = 0; i < (int)(blockDim.x >> 5); i++) { S += rs[i]; SS += rss[i]; }
        rs[0] = S; rss[0] = SS;
    }
    __syncthreads();
    float m    = rs[0] / (float)W;
    float var  = rss[0] / (float)W - m * m;
    float rstd = rsqrtf(var + 1e-5f);
    __syncthreads();
    float s2 = 0.f, ss2 = 0.f;
    const float* r = res + (long)row * W;
    float* xo = xout + (long)row * W;
    for (int i = threadIdx.x; i < W; i += blockDim.x) {
        float t = r[i] + (buf[i] - m) * rstd * g1[i] + b1[i];
        buf[i] = t; xo[i] = t; s2 += t; ss2 += t * t;
    }
    for (int o = 16; o; o >>= 1) { s2 += __shfl_down_sync(0xffffffffu, s2, o); ss2 += __shfl_down_sync(0xffffffffu, ss2, o); }
    if (!lid) { rs[wid] = s2; rss[wid] = ss2; }
    __syncthreads();
    if (threadIdx.x == 0) {
        float S = 0.f, SS = 0.f;
        for (int i = 0; i < (int)(blockDim.x >> 5); i++) { S += rs[i]; SS += rss[i]; }
        rs[0] = S; rss[0] = SS;
    }
    __syncthreads();
    float m2    = rs[0] / (float)W;
    float var2  = rss[0] / (float)W - m2 * m2;
    float rstd2 = rsqrtf(var2 + 1e-5f);
    float* yo = yout + (long)row * W;
    for (int i = threadIdx.x; i < W; i += blockDim.x)
        yo[i] = (buf[i] - m2) * rstd2 * g2[i] + b2[i];
}

__global__ void reduce_gelu_ln(const float* __restrict__ part,
                               const float* __restrict__ g, const float* __restrict__ b,
                               float* __restrict__ out) {
    const int W = GDIM;
    __shared__ float buf[GDIM];
    __shared__ float rs[32], rss[32];
    int row = blockIdx.x;
    float s = 0.f, ss = 0.f;
    for (int i = threadIdx.x; i < W; i += blockDim.x) {
        float a = 0.f, c = 0.f;
        #pragma unroll
        for (int k = 0; k < SPLITS; k++) {
            a += part[(long)k * B64 * W + (long)row * W + i];
            c += part[(long)(SPLITS + k) * B64 * W + (long)row * W + i];
        }
        float gl = 0.5f * a * (1.f + erff(a * 0.70710678118654752f));
        float v = gl * c;
        buf[i] = v; s += v; ss += v * v;
    }
    int wid = threadIdx.x >> 5, lid = threadIdx.x & 31;
    for (int o = 16; o; o >>= 1) { s += __shfl_down_sync(0xffffffffu, s, o); ss += __shfl_down_sync(0xffffffffu, ss, o); }
    if (!lid) { rs[wid] = s; rss[wid] = ss; }
    __syncthreads();
    if (threadIdx.x == 0) {
        float S = 0.f, SS = 0.f;
        for (int i = 0; i < (int)(blockDim.x >> 5); i++) { S += rs[i]; SS += rss[i]; }
        rs[0] = S; rss[0] = SS;
    }
    __syncthreads();
    float m    = rs[0] / (float)W;
    float var  = rss[0] / (float)W - m * m;
    float rstd = rsqrtf(var + 1e-5f);
    float* o = out + (long)row * W;
    for (int i = threadIdx.x; i < W; i += blockDim.x)
        o[i] = (buf[i] - m) * rstd * g[i] + b[i];
}

__global__ void reduce_add(const float* __restrict__ part, const float* __restrict__ res,
                           float* __restrict__ o) {
    int i = blockIdx.x * blockDim.x + threadIdx.x;
    if (i >= B64 * EMB) return;
    float s = 0.f;
    #pragma unroll
    for (int k = 0; k < SPLITS; k++) s += part[(long)k * B64 * EMB + i];
    o[i] = res[i] + s;
}

__global__ void reduce_one(const float* __restrict__ part, float* __restrict__ o, long WN) {
    for (long i = (long)blockIdx.x * blockDim.x + threadIdx.x; i < WN;
         i += (long)gridDim.x * blockDim.x) {
        float s = 0.f;
        #pragma unroll
        for (int k = 0; k < SPLITS; k++) s += part[(long)k * WN + i];
        o[i] = s;
    }
}

// ---------------- self-attention (one block per (b,h)) ----------------
__global__ void attn_kernel(const float* __restrict__ Q, const float* __restrict__ Kv,
                            const float* __restrict__ Vv, float* __restrict__ O,
                            int Srow, int Lfixed, const int* __restrict__ tokp) {
    int b = blockIdx.x, h = blockIdx.y;
    int L = tokp ? (*tokp + 1) : Lfixed;
    __shared__ float qsh[HC];
    __shared__ float sc[SKV];
    __shared__ float red[128];
    int tid = threadIdx.x;
    if (tid < HC) qsh[tid] = Q[(long)b * EMB + h * HC + tid];
    __syncthreads();

    int warp = tid >> 5, lane = tid & 31;
    for (int j = warp; j < L; j += 4) {
        const float* kp = Kv + ((long)b * Srow + j) * EMB + h * HC;
        float d = qsh[lane] * kp[lane] + qsh[lane + 32] * kp[lane + 32];
        for (int o = 16; o; o >>= 1) d += __shfl_down_sync(0xffffffffu, d, o);
        if (!lane) sc[j] = d * 0.125f;
    }
    __syncthreads();

    float mx = -1e30f;
    for (int j = tid; j < L; j += 128) mx = fmaxf(mx, sc[j]);
    red[tid] = mx; __syncthreads();
    for (int st = 64; st; st >>= 1) { if (tid < st) red[tid] = fmaxf(red[tid], red[tid + st]); __syncthreads(); }
    mx = red[0];
    __syncthreads();

    float sum = 0.f;
    for (int j = tid; j < L; j += 128) { float e = expf(sc[j] - mx); sc[j] = e; sum += e; }
    red[tid] = sum; __syncthreads();
    for (int st = 64; st; st >>= 1) { if (tid < st) red[tid] += red[tid + st]; __syncthreads(); }
    float inv = 1.f / red[0];

    if (tid < HC) {
        float acc = 0.f;
        const float* vb = Vv + (long)b * Srow * EMB + h * HC + tid;
        for (int j = 0; j < L; j++) acc += sc[j] * vb[(long)j * EMB];
        O[(long)b * EMB + h * HC + tid] = acc * inv;
    }
}

// ---------------- host orchestration ----------------
extern "C" void kernel_launch(void* const* d_in, const int* in_sizes, int n_in,
                              void* d_out, int out_size) {
    const float* dec        = (const float*)d_in[0];
    const float* enc        = (const float*)d_in[1];
    const float* astate     = (const float*)d_in[2];
    const int*   tokp       = (const int*)d_in[4];
    const float* ln_pre_sa_g = (const float*)d_in[5];
    const float* ln_pre_sa_b = (const float*)d_in[6];
    const float* ln_sa_g     = (const float*)d_in[7];
    const float* ln_sa_b     = (const float*)d_in[8];
    const float* ln_pre_ca_g = (const float*)d_in[9];
    const float* ln_pre_ca_b = (const float*)d_in[10];
    const float* ln_ca_g     = (const float*)d_in[11];
    const float* ln_ca_b     = (const float*)d_in[12];
    const float* sa_wq = (const float*)d_in[13];
    const float* sa_wk = (const float*)d_in[14];
    const float* sa_wv = (const float*)d_in[15];
    const float* sa_wo = (const float*)d_in[16];
    const float* ca_wq = (const float*)d_in[17];
    const float* ca_wk = (const float*)d_in[18];
    const float* ca_wv = (const float*)d_in[19];
    const float* ca_wo = (const float*)d_in[20];
    const float* glu_ln0_g = (const float*)d_in[21];
    const float* glu_ln0_b = (const float*)d_in[22];
    const float* glu_fc0   = (const float*)d_in[23];
    const float* glu_fc1   = (const float*)d_in[24];
    const float* glu_ln1_g = (const float*)d_in[25];
    const float* glu_ln1_b = (const float*)d_in[26];
    const float* glu_fc2   = (const float*)d_in[27];

    float* out       = (float*)d_out;
    float* out_x     = out;
    float* out_state = out + (long)B64 * EMB;

    float *x1, *qkv, *attnout, *x2, *y1, *qc, *x3, *z1, *gln, *part, *vpart;
    __half *ench, *qkh, *ctxh;
    cudaGetSymbolAddress((void**)&x1, g_x1);
    cudaGetSymbolAddress((void**)&qkv, g_qkv);
    cudaGetSymbolAddress((void**)&attnout, g_attnout);
    cudaGetSymbolAddress((void**)&x2, g_x2);
    cudaGetSymbolAddress((void**)&y1, g_y1);
    cudaGetSymbolAddress((void**)&qc, g_qc);
    cudaGetSymbolAddress((void**)&x3, g_x3);
    cudaGetSymbolAddress((void**)&z1, g_z1);
    cudaGetSymbolAddress((void**)&gln, g_gln);
    cudaGetSymbolAddress((void**)&part, g_partial);
    cudaGetSymbolAddress((void**)&vpart, g_vpart);
    cudaGetSymbolAddress((void**)&ench, g_ench);
    cudaGetSymbolAddress((void**)&qkh, g_qk);
    cudaGetSymbolAddress((void**)&ctxh, g_ctx);

    // 0. fused: state copy + enc fp16 convert
    long n4 = (long)2 * B64 * SKV * EMB / 4;
    long ne = (long)B64 * TENC * EMB / 4;
    copy_cvt<<<4096, 256>>>((const float4*)astate, (float4*)out_state, n4,
                            (const float4*)enc, (uint2*)ench, ne);

    // 1. x1 = LN(decoder_state)
    ln_kernel<<<B64, 256>>>(dec, ln_pre_sa_g, ln_pre_sa_b, nullptr, x1, EMB);

    // 2-3. q/k/v projections -> fused reduce + cache scatter
    wmma_small<<<dim3(EMB / 128, SPLITS, 3), 256>>>(x1, sa_wq, sa_wk, sa_wv, part, EMB, EMB);
    reduce_qkv_scatter<<<(3 * B64 * EMB) / 256, 256>>>(part, qkv, out_state, tokp);

    // 4. self-attention over updated cache
    attn_kernel<<<dim3(B64, NH), 128>>>(qkv, out_state, out_state + (long)B64 * SKV * EMB,
                                        attnout, SKV, 0, tokp);

    // 5. sa out-proj -> fused reduce+LN+res (x2) + LN_pre_ca (y1)
    wmma_small<<<dim3(EMB / 128, SPLITS, 1), 256>>>(attnout, sa_wo, sa_wo, sa_wo, part, EMB, EMB);
    reduce_ln_ln<<<B64, 256>>>(part, ln_sa_g, ln_sa_b, dec, ln_pre_ca_g, ln_pre_ca_b, x2, y1);

    // 6. cross-attention via associativity (no giant GEMMs)
    wmma_small<<<dim3(EMB / 128, SPLITS, 1), 256>>>(y1, ca_wq, ca_wq, ca_wq, part, EMB, EMB);
    reduce_one<<<512, 256>>>(part, qc, (long)B64 * EMB);
    qk_gemm<<<dim3(16, NH), 256>>>(qc, ca_wk, qkh);
    cross_attn<<<B64, 256>>>(qkh, ench, ctxh);
    outv_gemm<<<dim3(NH, 4), 256>>>(ctxh, ca_wv, vpart);
    reduce_outv<<<(B64 * EMB) / 256, 256>>>(vpart, attnout);

    // 7. ca out-proj -> fused reduce+LN+res (x3) + LN_glu0 (z1)
    wmma_small<<<dim3(EMB / 128, SPLITS, 1), 256>>>(attnout, ca_wo, ca_wo, ca_wo, part, EMB, EMB);
    reduce_ln_ln<<<B64, 256>>>(part, ln_ca_g, ln_ca_b, x2, glu_ln0_g, glu_ln0_b, x3, z1);

    // 8. GLU block
    wmma_small<<<dim3(GDIM / 128, SPLITS, 2), 256>>>(z1, glu_fc0, glu_fc1, glu_fc1, part, GDIM, EMB);
    reduce_gelu_ln<<<B64, 256>>>(part, glu_ln1_g, glu_ln1_b, gln);
    wmma_small<<<dim3(EMB / 128, SPLITS, 1), 256>>>(gln, glu_fc2, glu_fc2, glu_fc2, part, EMB, GDIM);
    reduce_add<<<512, 256>>>(part, x3, out_x);
}

// round 13
// speedup vs baseline: 1.5456x; 1.3149x over previous
#include <cuda_runtime.h>
#include <cuda_fp16.h>
#include <mma.h>
#include <math.h>
#include <stdint.h>

using namespace nvcuda;

#define B64   64
#define EMB   2048
#define GDIM  4096
#define TENC  64
#define SKV   256
#define NH    32
#define HC    64
#define SPLITS 8

// ---------------- scratch ----------------
__device__ float g_x1[B64*EMB];
__device__ float g_q[B64*EMB];
__device__ float g_kvnew[2*B64*EMB];
__device__ float g_attnout[B64*EMB];
__device__ float g_x2[B64*EMB];
__device__ float g_y1[B64*EMB];
__device__ float g_x3[B64*EMB];
__device__ float g_z1[B64*EMB];
__device__ float g_gln[B64*GDIM];
__device__ float g_partial[3*SPLITS*B64*GDIM];
__device__ float g_vpart[NH*4*HC*B64];
__device__ __half g_ench[B64*TENC*EMB];
__device__ __half g_qk[B64*NH*EMB];
__device__ __half g_ctx[B64*NH*EMB];

__device__ __forceinline__ uint2 pack4h(float4 v) {
    __half2 h0 = __floats2half2_rn(v.x, v.y);
    __half2 h1 = __floats2half2_rn(v.z, v.w);
    uint2 u;
    u.x = *(uint32_t*)&h0;
    u.y = *(uint32_t*)&h1;
    return u;
}

// ---------------- layernorm ----------------
__global__ void ln_kernel(const float* __restrict__ in, const float* __restrict__ g,
                          const float* __restrict__ b, const float* __restrict__ res,
                          float* __restrict__ out, int W) {
    int row = blockIdx.x;
    const float* x = in + (long)row * W;
    float s = 0.f, ss = 0.f;
    for (int i = threadIdx.x; i < W; i += blockDim.x) { float v = x[i]; s += v; ss += v * v; }
    __shared__ float rs[32], rss[32];
    for (int o = 16; o; o >>= 1) { s += __shfl_down_sync(0xffffffffu, s, o); ss += __shfl_down_sync(0xffffffffu, ss, o); }
    int wid = threadIdx.x >> 5, lid = threadIdx.x & 31;
    if (!lid) { rs[wid] = s; rss[wid] = ss; }
    __syncthreads();
    if (threadIdx.x == 0) {
        float S = 0.f, SS = 0.f;
        int nw = blockDim.x >> 5;
        for (int i = 0; i < nw; i++) { S += rs[i]; SS += rss[i]; }
        rs[0] = S; rss[0] = SS;
    }
    __syncthreads();
    float m    = rs[0] / (float)W;
    float var  = rss[0] / (float)W - m * m;
    float rstd = rsqrtf(var + 1e-5f);
    float* o = out + (long)row * W;
    const float* r = res ? res + (long)row * W : nullptr;
    for (int i = threadIdx.x; i < W; i += blockDim.x) {
        float v = (x[i] - m) * rstd * g[i] + b[i];
        o[i] = r ? (r[i] + v) : v;
    }
}

// ---------------- small GEMM with side-work planes ----------------
// compute blocks: blockIdx.z < nW. z==nW: float4 copy of [cb,ce). z==nW+1: fp16 cvt of [0,vn).
__global__ __launch_bounds__(256) void wmma_small(
    const float* __restrict__ A, const float* __restrict__ Wa,
    const float* __restrict__ Wb, const float* __restrict__ Wc,
    float* __restrict__ part, int N, int K, int nW,
    const float4* __restrict__ csrc, float4* __restrict__ cdst, long cb, long ce,
    const float4* __restrict__ vsrc, uint2* __restrict__ vdst, long vn) {
    int zw = blockIdx.z;
    if (zw >= nW) {
        int role = zw - nW;
        long nb = (long)gridDim.x * gridDim.y;
        long sid = (long)blockIdx.y * gridDim.x + blockIdx.x;
        long stride = nb * blockDim.x;
        if (role == 0) {
            for (long i = cb + sid * blockDim.x + threadIdx.x; i < ce; i += stride)
                cdst[i] = csrc[i];
        } else {
            for (long i = sid * blockDim.x + threadIdx.x; i < vn; i += stride)
                vdst[i] = pack4h(vsrc[i]);
        }
        return;
    }
    int nt = blockIdx.x, s = blockIdx.y, w = zw;
    const float* W = (w == 0) ? Wa : ((w == 1) ? Wb : Wc);
    int Ks = K / SPLITS;
    int k0 = s * Ks;
    int n0 = nt * 128;
    __shared__ __align__(16) __half As[2][64][40];
    __shared__ __align__(16) __half Bs[2][32][136];
    int tid = threadIdx.x;
    int warp = tid >> 5;
    int wm = warp >> 1;
    int wn = warp & 1;

    wmma::fragment<wmma::accumulator, 16, 16, 16, float> c[4];
    #pragma unroll
    for (int j = 0; j < 4; j++) wmma::fill_fragment(c[j], 0.f);

    float4 ra[2], rb[4];
    int ar[2], ac[2], br[4], bc[4];
    #pragma unroll
    for (int u = 0; u < 2; u++) {
        int idx = tid + u * 256;
        ar[u] = idx >> 3;  ac[u] = (idx & 7) * 4;
    }
    #pragma unroll
    for (int u = 0; u < 4; u++) {
        int idx = tid + u * 256;
        br[u] = idx >> 5;  bc[u] = (idx & 31) * 4;
    }
    auto loadG = [&](int kt) {
        #pragma unroll
        for (int u = 0; u < 2; u++)
            ra[u] = *(const float4*)(A + (long)ar[u] * K + k0 + kt + ac[u]);
        #pragma unroll
        for (int u = 0; u < 4; u++)
            rb[u] = *(const float4*)(W + (long)(k0 + kt + br[u]) * N + n0 + bc[u]);
    };
    auto storeS = [&](int buf) {
        #pragma unroll
        for (int u = 0; u < 2; u++)
            *(uint2*)&As[buf][ar[u]][ac[u]] = pack4h(ra[u]);
        #pragma unroll
        for (int u = 0; u < 4; u++)
            *(uint2*)&Bs[buf][br[u]][bc[u]] = pack4h(rb[u]);
    };

    loadG(0);
    storeS(0);
    __syncthreads();
    int buf = 0;

    for (int kt = 0; kt < Ks; kt += 32) {
        int nxt = kt + 32;
        if (nxt < Ks) loadG(nxt);
        #pragma unroll
        for (int k16 = 0; k16 < 32; k16 += 16) {
            wmma::fragment<wmma::matrix_a, 16, 16, 16, __half, wmma::row_major> a;
            wmma::load_matrix_sync(a, &As[buf][wm * 16][k16], 40);
            #pragma unroll
            for (int j = 0; j < 4; j++) {
                wmma::fragment<wmma::matrix_b, 16, 16, 16, __half, wmma::row_major> b;
                wmma::load_matrix_sync(b, &Bs[buf][k16][wn * 64 + j * 16], 136);
                wmma::mma_sync(c[j], a, b, c[j]);
            }
        }
        if (nxt < Ks) storeS(buf ^ 1);
        __syncthreads();
        buf ^= 1;
    }
    float* P = part + (long)(w * SPLITS + s) * 64 * N;
    #pragma unroll
    for (int j = 0; j < 4; j++)
        wmma::store_matrix_sync(P + (long)(wm * 16) * N + n0 + wn * 64 + j * 16,
                                c[j], N, wmma::mem_row_major);
}

// ---------------- qk_gemm (reads q split-K partials directly) ----------------
// qk[b,h,e] = sum_c q[b,h*64+c] * Wk[e,h*64+c]; grid (16 e-tiles, 32 h)
__global__ __launch_bounds__(256) void qk_gemm(const float* __restrict__ part,
                                               const float* __restrict__ Wk,
                                               __half* __restrict__ qk) {
    int e0 = blockIdx.x * 128, h = blockIdx.y;
    __shared__ __align__(16) __half As[64][72];
    __shared__ __align__(16) __half Bs[128][72];
    __shared__ float patch[8][16][20];
    int tid = threadIdx.x;
    int warp = tid >> 5, lane = tid & 31;
    int wm = warp >> 1;
    int wn = warp & 1;

    #pragma unroll
    for (int u = 0; u < 4; u++) {
        int idx = tid + u * 256;
        int b = idx >> 4, c4 = (idx & 15) * 4;
        float4 acc = make_float4(0.f, 0.f, 0.f, 0.f);
        #pragma unroll
        for (int k = 0; k < SPLITS; k++) {
            float4 v = *(const float4*)(part + (long)k * B64 * EMB + (long)b * EMB + h * 64 + c4);
            acc.x += v.x; acc.y += v.y; acc.z += v.z; acc.w += v.w;
        }
        *(uint2*)&As[b][c4] = pack4h(acc);
    }
    #pragma unroll
    for (int u = 0; u < 8; u++) {
        int idx = tid + u * 256;
        int e = idx >> 4, c4 = (idx & 15) * 4;
        float4 v = *(const float4*)(Wk + (long)(e0 + e) * EMB + h * 64 + c4);
        *(uint2*)&Bs[e][c4] = pack4h(v);
    }
    __syncthreads();

    wmma::fragment<wmma::accumulator, 16, 16, 16, float> c[4];
    #pragma unroll
    for (int j = 0; j < 4; j++) wmma::fill_fragment(c[j], 0.f);
    #pragma unroll
    for (int k16 = 0; k16 < 64; k16 += 16) {
        wmma::fragment<wmma::matrix_a, 16, 16, 16, __half, wmma::row_major> a;
        wmma::load_matrix_sync(a, &As[wm * 16][k16], 72);
        #pragma unroll
        for (int j = 0; j < 4; j++) {
            wmma::fragment<wmma::matrix_b, 16, 16, 16, __half, wmma::col_major> b;
            wmma::load_matrix_sync(b, &Bs[wn * 64 + j * 16][k16], 72);
            wmma::mma_sync(c[j], a, b, c[j]);
        }
    }
    #pragma unroll
    for (int j = 0; j < 4; j++) {
        wmma::store_matrix_sync(&patch[warp][0][0], c[j], 20, wmma::mem_row_major);
        __syncwarp();
        int r = lane >> 1, c0 = (lane & 1) * 8;
        float* p = &patch[warp][r][c0];
        __half2 h0 = __floats2half2_rn(p[0], p[1]);
        __half2 h1 = __floats2half2_rn(p[2], p[3]);
        __half2 h2 = __floats2half2_rn(p[4], p[5]);
        __half2 h3 = __floats2half2_rn(p[6], p[7]);
        uint4 pk = make_uint4(*(uint32_t*)&h0, *(uint32_t*)&h1, *(uint32_t*)&h2, *(uint32_t*)&h3);
        int b = wm * 16 + r;
        long off = ((long)b * NH + h) * EMB + e0 + wn * 64 + j * 16 + c0;
        *(uint4*)(qk + off) = pk;
        __syncwarp();
    }
}

// ---------------- cross_attn: scores + softmax + ctx, one block per batch ----------
__global__ __launch_bounds__(256) void cross_attn(const __half* __restrict__ qk,
                                                  const __half* __restrict__ ench,
                                                  __half* __restrict__ ctx) {
    int b = blockIdx.x;
    int tid = threadIdx.x;
    int warp = tid >> 5, lane = tid & 31;
    const __half* A = qk + (long)b * NH * EMB;
    const __half* E = ench + (long)b * TENC * EMB;
    __shared__ float sc[32][72];
    __shared__ __half wsh[32][72];
    __shared__ float patch[8][16][20];

    {
        int wm = warp >> 2, wn = warp & 3;
        wmma::fragment<wmma::accumulator, 16, 16, 16, float> acc;
        wmma::fill_fragment(acc, 0.f);
        for (int k16 = 0; k16 < EMB; k16 += 16) {
            wmma::fragment<wmma::matrix_a, 16, 16, 16, __half, wmma::row_major> a;
            wmma::fragment<wmma::matrix_b, 16, 16, 16, __half, wmma::col_major> bb;
            wmma::load_matrix_sync(a, A + (long)(wm * 16) * EMB + k16, EMB);
            wmma::load_matrix_sync(bb, E + (long)(wn * 16) * EMB + k16, EMB);
            wmma::mma_sync(acc, a, bb, acc);
        }
        wmma::store_matrix_sync(&sc[wm * 16][wn * 16], acc, 72, wmma::mem_row_major);
    }
    __syncthreads();

    if (tid < 32) {
        float mx = -1e30f;
        #pragma unroll
        for (int k = 0; k < TENC; k++) mx = fmaxf(mx, sc[tid][k] * 0.125f);
        float sum = 0.f;
        float ex[TENC];
        #pragma unroll
        for (int k = 0; k < TENC; k++) { ex[k] = expf(sc[tid][k] * 0.125f - mx); sum += ex[k]; }
        float inv = 1.f / sum;
        #pragma unroll
        for (int k = 0; k < TENC; k++) wsh[tid][k] = __float2half(ex[k] * inv);
    }
    __syncthreads();

    {
        int wm = warp >> 2, wn = warp & 3;
        for (int nt = wn; nt < 128; nt += 4) {
            wmma::fragment<wmma::accumulator, 16, 16, 16, float> acc;
            wmma::fill_fragment(acc, 0.f);
            #pragma unroll
            for (int kk = 0; kk < TENC; kk += 16) {
                wmma::fragment<wmma::matrix_a, 16, 16, 16, __half, wmma::row_major> a;
                wmma::fragment<wmma::matrix_b, 16, 16, 16, __half, wmma::row_major> bb;
                wmma::load_matrix_sync(a, &wsh[wm * 16][kk], 72);
                wmma::load_matrix_sync(bb, E + (long)kk * EMB + nt * 16, EMB);
                wmma::mma_sync(acc, a, bb, acc);
            }
            wmma::store_matrix_sync(&patch[warp][0][0], acc, 20, wmma::mem_row_major);
            __syncwarp();
            int r = lane >> 1, c0 = (lane & 1) * 8;
            float* p = &patch[warp][r][c0];
            __half2 h0 = __floats2half2_rn(p[0], p[1]);
            __half2 h1 = __floats2half2_rn(p[2], p[3]);
            __half2 h2 = __floats2half2_rn(p[4], p[5]);
            __half2 h3 = __floats2half2_rn(p[6], p[7]);
            uint4 pk = make_uint4(*(uint32_t*)&h0, *(uint32_t*)&h1, *(uint32_t*)&h2, *(uint32_t*)&h3);
            int h = wm * 16 + r;
            long off = ((long)b * NH + h) * EMB + nt * 16 + c0;
            *(uint4*)(ctx + off) = pk;
            __syncwarp();
        }
    }
}

// ---------------- outv_gemm ----------------
__global__ __launch_bounds__(256) void outv_gemm(const __half* __restrict__ ctx,
                                                 const float* __restrict__ Wv,
                                                 float* __restrict__ part) {
    int h = blockIdx.x, s = blockIdx.y;
    int k0 = s * 512;
    __shared__ __align__(16) __half Bs[32][72];
    int tid = threadIdx.x;
    int warp = tid >> 5;
    int wm = warp >> 1;
    int wn = warp & 1;
    const __half* A = ctx + (long)h * EMB + k0;

    wmma::fragment<wmma::accumulator, 16, 16, 16, float> c[2];
    wmma::fill_fragment(c[0], 0.f);
    wmma::fill_fragment(c[1], 0.f);

    for (int kt = 0; kt < 512; kt += 32) {
        #pragma unroll
        for (int u = 0; u < 2; u++) {
            int idx = tid + u * 256;
            int e = idx >> 4, c4 = (idx & 15) * 4;
            float4 v = *(const float4*)(Wv + (long)(k0 + kt + e) * EMB + h * 64 + c4);
            *(uint2*)&Bs[e][c4] = pack4h(v);
        }
        __syncthreads();
        #pragma unroll
        for (int k16 = 0; k16 < 32; k16 += 16) {
            wmma::fragment<wmma::matrix_a, 16, 16, 16, __half, wmma::row_major> a;
            wmma::load_matrix_sync(a, A + (long)(wm * 16) * (NH * EMB) + kt + k16, NH * EMB);
            #pragma unroll
            for (int j = 0; j < 2; j++) {
                wmma::fragment<wmma::matrix_b, 16, 16, 16, __half, wmma::row_major> bb;
                wmma::load_matrix_sync(bb, &Bs[k16][wn * 32 + j * 16], 72);
                wmma::mma_sync(c[j], a, bb, c[j]);
            }
        }
        __syncthreads();
    }
    float* P = part + (long)(h * 4 + s) * 4096;
    #pragma unroll
    for (int j = 0; j < 2; j++)
        wmma::store_matrix_sync(P + (long)(wm * 16) * 64 + wn * 32 + j * 16,
                                c[j], 64, wmma::mem_row_major);
}

__global__ void reduce_outv(const float* __restrict__ part, float* __restrict__ attnout) {
    int idx = blockIdx.x * blockDim.x + threadIdx.x;
    if (idx >= B64 * EMB) return;
    int b = idx >> 11, r = idx & (EMB - 1);
    int h = r >> 6, cc = r & 63;
    float s = 0.f;
    #pragma unroll
    for (int k = 0; k < 4; k++) s += part[(long)(h * 4 + k) * 4096 + b * 64 + cc];
    attnout[idx] = s;
}

// ---------------- fused epilogues ----------------
// q + kv_new into scratch (no out_state dependency)
__global__ void reduce_qkv(const float* __restrict__ part, float* __restrict__ q,
                           float* __restrict__ kvnew) {
    int idx = blockIdx.x * blockDim.x + threadIdx.x;
    if (idx >= 3 * B64 * EMB) return;
    int w = idx / (B64 * EMB);
    int rem = idx - w * B64 * EMB;
    float s = 0.f;
    #pragma unroll
    for (int k = 0; k < SPLITS; k++) s += part[(long)(w * SPLITS + k) * B64 * EMB + rem];
    if (w == 0) q[rem] = s;
    else kvnew[(long)(w - 1) * B64 * EMB + rem] = s;
}

__global__ void reduce_ln_ln(const float* __restrict__ part,
                             const float* __restrict__ g1, const float* __restrict__ b1,
                             const float* __restrict__ res,
                             const float* __restrict__ g2, const float* __restrict__ b2,
                             float* __restrict__ xout, float* __restrict__ yout) {
    const int W = EMB;
    __shared__ float buf[EMB];
    __shared__ float rs[32], rss[32];
    int row = blockIdx.x;
    float s = 0.f, ss = 0.f;
    for (int i = threadIdx.x; i < W; i += blockDim.x) {
        float v = 0.f;
        #pragma unroll
        for (int k = 0; k < SPLITS; k++) v += part[(long)k * B64 * W + (long)row * W + i];
        buf[i] = v; s += v; ss += v * v;
    }
    int wid = threadIdx.x >> 5, lid = threadIdx.x & 31;
    for (int o = 16; o; o >>= 1) { s += __shfl_down_sync(0xffffffffu, s, o); ss += __shfl_down_sync(0xffffffffu, ss, o); }
    if (!lid) { rs[wid] = s; rss[wid] = ss; }
    __syncthreads();
    if (threadIdx.x == 0) {
        float S = 0.f, SS = 0.f;
        for (int i = 0; i < (int)(blockDim.x >> 5); i++) { S += rs[i]; SS += rss[i]; }
        rs[0] = S; rss[0] = SS;
    }
    __syncthreads();
    float m    = rs[0] / (float)W;
    float var  = rss[0] / (float)W - m * m;
    float rstd = rsqrtf(var + 1e-5f);
    __syncthreads();
    float s2 = 0.f, ss2 = 0.f;
    const float* r = res + (long)row * W;
    float* xo = xout + (long)row * W;
    for (int i = threadIdx.x; i < W; i += blockDim.x) {
        float t = r[i] + (buf[i] - m) * rstd * g1[i] + b1[i];
        buf[i] = t; xo[i] = t; s2 += t; ss2 += t * t;
    }
    for (int o = 16; o; o >>= 1) { s2 += __shfl_down_sync(0xffffffffu, s2, o); ss2 += __shfl_down_sync(0xffffffffu, ss2, o); }
    if (!lid) { rs[wid] = s2; rss[wid] = ss2; }
    __syncthreads();
    if (threadIdx.x == 0) {
        float S = 0.f, SS = 0.f;
        for (int i = 0; i < (int)(blockDim.x >> 5); i++) { S += rs[i]; SS += rss[i]; }
        rs[0] = S; rss[0] = SS;
    }
    __syncthreads();
    float m2    = rs[0] / (float)W;
    float var2  = rss[0] / (float)W - m2 * m2;
    float rstd2 = rsqrtf(var2 + 1e-5f);
    float* yo = yout + (long)row * W;
    for (int i = threadIdx.x; i < W; i += blockDim.x)
        yo[i] = (buf[i] - m2) * rstd2 * g2[i] + b2[i];
}

__global__ void reduce_gelu_ln(const float* __restrict__ part,
                               const float* __restrict__ g, const float* __restrict__ b,
                               float* __restrict__ out) {
    const int W = GDIM;
    __shared__ float buf[GDIM];
    __shared__ float rs[32], rss[32];
    int row = blockIdx.x;
    float s = 0.f, ss = 0.f;
    for (int i = threadIdx.x; i < W; i += blockDim.x) {
        float a = 0.f, c = 0.f;
        #pragma unroll
        for (int k = 0; k < SPLITS; k++) {
            a += part[(long)k * B64 * W + (long)row * W + i];
            c += part[(long)(SPLITS + k) * B64 * W + (long)row * W + i];
        }
        float gl = 0.5f * a * (1.f + erff(a * 0.70710678118654752f));
        float v = gl * c;
        buf[i] = v; s += v; ss += v * v;
    }
    int wid = threadIdx.x >> 5, lid = threadIdx.x & 31;
    for (int o = 16; o; o >>= 1) { s += __shfl_down_sync(0xffffffffu, s, o); ss += __shfl_down_sync(0xffffffffu, ss, o); }
    if (!lid) { rs[wid] = s; rss[wid] = ss; }
    __syncthreads();
    if (threadIdx.x == 0) {
        float S = 0.f, SS = 0.f;
        for (int i = 0; i < (int)(blockDim.x >> 5); i++) { S += rs[i]; SS += rss[i]; }
        rs[0] = S; rss[0] = SS;
    }
    __syncthreads();
    float m    = rs[0] / (float)W;
    float var  = rss[0] / (float)W - m * m;
    float rstd = rsqrtf(var + 1e-5f);
    float* o = out + (long)row * W;
    for (int i = threadIdx.x; i < W; i += blockDim.x)
        o[i] = (buf[i] - m) * rstd * g[i] + b[i];
}

// final: reduce+residual for x output AND token-row scatter into out_state
__global__ void reduce_add_scatter(const float* __restrict__ part, const float* __restrict__ res,
                                   float* __restrict__ out_x, const float* __restrict__ kvnew,
                                   float* __restrict__ outstate, const int* __restrict__ tokp) {
    int idx = blockIdx.x * blockDim.x + threadIdx.x;
    if (idx < B64 * EMB) {
        float s = 0.f;
        #pragma unroll
        for (int k = 0; k < SPLITS; k++) s += part[(long)k * B64 * EMB + idx];
        out_x[idx] = res[idx] + s;
    } else {
        int j = idx - B64 * EMB;
        if (j < 2 * B64 * EMB) {
            int tok = *tokp;
            int bb = j >> 11, e = j & (EMB - 1);
            outstate[((long)bb * SKV + tok) * EMB + e] = kvnew[j];
        }
    }
}

// ---------------- self-attention: reads astate directly + kvnew for token row ------
__global__ void self_attn(const float* __restrict__ Q, const float* __restrict__ astate,
                          const float* __restrict__ kvnew, float* __restrict__ O,
                          const int* __restrict__ tokp) {
    int b = blockIdx.x, h = blockIdx.y;
    int tok = *tokp;
    int L = tok + 1;
    __shared__ float qsh[HC];
    __shared__ float sc[SKV];
    __shared__ float red[128];
    int tid = threadIdx.x;
    if (tid < HC) qsh[tid] = Q[(long)b * EMB + h * HC + tid];
    __syncthreads();

    int warp = tid >> 5, lane = tid & 31;
    for (int j = warp; j < L; j += 4) {
        const float* kp = (j == tok)
            ? kvnew + (long)b * EMB + h * HC
            : astate + ((long)b * SKV + j) * EMB + h * HC;
        float d = qsh[lane] * kp[lane] + qsh[lane + 32] * kp[lane + 32];
        for (int o = 16; o; o >>= 1) d += __shfl_down_sync(0xffffffffu, d, o);
        if (!lane) sc[j] = d * 0.125f;
    }
    __syncthreads();

    float mx = -1e30f;
    for (int j = tid; j < L; j += 128) mx = fmaxf(mx, sc[j]);
    red[tid] = mx; __syncthreads();
    for (int st = 64; st; st >>= 1) { if (tid < st) red[tid] = fmaxf(red[tid], red[tid + st]); __syncthreads(); }
    mx = red[0];
    __syncthreads();

    float sum = 0.f;
    for (int j = tid; j < L; j += 128) { float e = expf(sc[j] - mx); sc[j] = e; sum += e; }
    red[tid] = sum; __syncthreads();
    for (int st = 64; st; st >>= 1) { if (tid < st) red[tid] += red[tid + st]; __syncthreads(); }
    float inv = 1.f / red[0];

    if (tid < HC) {
        float acc = 0.f;
        const float* vbase = astate + ((long)(B64 + b) * SKV) * EMB + h * HC + tid;
        for (int j = 0; j < tok; j++) acc += sc[j] * vbase[(long)j * EMB];
        acc += sc[tok] * kvnew[(long)(B64 + b) * EMB + h * HC + tid];
        O[(long)b * EMB + h * HC + tid] = acc * inv;
    }
}

// ---------------- host orchestration ----------------
extern "C" void kernel_launch(void* const* d_in, const int* in_sizes, int n_in,
                              void* d_out, int out_size) {
    const float* dec        = (const float*)d_in[0];
    const float* enc        = (const float*)d_in[1];
    const float* astate     = (const float*)d_in[2];
    const int*   tokp       = (const int*)d_in[4];
    const float* ln_pre_sa_g = (const float*)d_in[5];
    const float* ln_pre_sa_b = (const float*)d_in[6];
    const float* ln_sa_g     = (const float*)d_in[7];
    const float* ln_sa_b     = (const float*)d_in[8];
    const float* ln_pre_ca_g = (const float*)d_in[9];
    const float* ln_pre_ca_b = (const float*)d_in[10];
    const float* ln_ca_g     = (const float*)d_in[11];
    const float* ln_ca_b     = (const float*)d_in[12];
    const float* sa_wq = (const float*)d_in[13];
    const float* sa_wk = (const float*)d_in[14];
    const float* sa_wv = (const float*)d_in[15];
    const float* sa_wo = (const float*)d_in[16];
    const float* ca_wq = (const float*)d_in[17];
    const float* ca_wk = (const float*)d_in[18];
    const float* ca_wv = (const float*)d_in[19];
    const float* ca_wo = (const float*)d_in[20];
    const float* glu_ln0_g = (const float*)d_in[21];
    const float* glu_ln0_b = (const float*)d_in[22];
    const float* glu_fc0   = (const float*)d_in[23];
    const float* glu_fc1   = (const float*)d_in[24];
    const float* glu_ln1_g = (const float*)d_in[25];
    const float* glu_ln1_b = (const float*)d_in[26];
    const float* glu_fc2   = (const float*)d_in[27];

    float* out       = (float*)d_out;
    float* out_x     = out;
    float* out_state = out + (long)B64 * EMB;

    float *x1, *q, *kvnew, *attnout, *x2, *y1, *x3, *z1, *gln, *part, *vpart;
    __half *ench, *qkh, *ctxh;
    cudaGetSymbolAddress((void**)&x1, g_x1);
    cudaGetSymbolAddress((void**)&q, g_q);
    cudaGetSymbolAddress((void**)&kvnew, g_kvnew);
    cudaGetSymbolAddress((void**)&attnout, g_attnout);
    cudaGetSymbolAddress((void**)&x2, g_x2);
    cudaGetSymbolAddress((void**)&y1, g_y1);
    cudaGetSymbolAddress((void**)&x3, g_x3);
    cudaGetSymbolAddress((void**)&z1, g_z1);
    cudaGetSymbolAddress((void**)&gln, g_gln);
    cudaGetSymbolAddress((void**)&part, g_partial);
    cudaGetSymbolAddress((void**)&vpart, g_vpart);
    cudaGetSymbolAddress((void**)&ench, g_ench);
    cudaGetSymbolAddress((void**)&qkh, g_qk);
    cudaGetSymbolAddress((void**)&ctxh, g_ctx);

    const float4* stsrc = (const float4*)astate;
    float4* stdst = (float4*)out_state;
    const long N4T = (long)2 * B64 * SKV * EMB / 4;    // 16,777,216
    const long NE  = (long)B64 * TENC * EMB / 4;       // enc float4 count
    // copy chunk boundaries distributed across gemm launches
    const long C0 = 2000000, C1 = 4500000, C2 = 7000000, C3 = 9500000, C4 = 14000000;

    // 1. x1 = LN(decoder_state)
    ln_kernel<<<B64, 256>>>(dec, ln_pre_sa_g, ln_pre_sa_b, nullptr, x1, EMB);

    // 2. qkv projections + side: copy chunk [0,C0) + enc fp16 convert
    wmma_small<<<dim3(EMB / 128, SPLITS, 3 + 2), 256>>>(
        x1, sa_wq, sa_wk, sa_wv, part, EMB, EMB, 3,
        stsrc, stdst, 0, C0, (const float4*)enc, (uint2*)ench, NE);
    reduce_qkv<<<(3 * B64 * EMB) / 256, 256>>>(part, q, kvnew);

    // 3. self-attention (reads astate input + kvnew scratch)
    self_attn<<<dim3(B64, NH), 128>>>(q, astate, kvnew, attnout, tokp);

    // 4. sa out-proj + side copy [C0,C1)
    wmma_small<<<dim3(EMB / 128, SPLITS, 1 + 1), 256>>>(
        attnout, sa_wo, sa_wo, sa_wo, part, EMB, EMB, 1,
        stsrc, stdst, C0, C1, nullptr, nullptr, 0);
    reduce_ln_ln<<<B64, 256>>>(part, ln_sa_g, ln_sa_b, dec, ln_pre_ca_g, ln_pre_ca_b, x2, y1);

    // 5. ca_wq + side copy [C1,C2); qk_gemm reads partials directly
    wmma_small<<<dim3(EMB / 128, SPLITS, 1 + 1), 256>>>(
        y1, ca_wq, ca_wq, ca_wq, part, EMB, EMB, 1,
        stsrc, stdst, C1, C2, nullptr, nullptr, 0);
    qk_gemm<<<dim3(16, NH), 256>>>(part, ca_wk, qkh);
    cross_attn<<<B64, 256>>>(qkh, ench, ctxh);
    outv_gemm<<<dim3(NH, 4), 256>>>(ctxh, ca_wv, vpart);
    reduce_outv<<<(B64 * EMB) / 256, 256>>>(vpart, attnout);

    // 6. ca out-proj + side copy [C2,C3)
    wmma_small<<<dim3(EMB / 128, SPLITS, 1 + 1), 256>>>(
        attnout, ca_wo, ca_wo, ca_wo, part, EMB, EMB, 1,
        stsrc, stdst, C2, C3, nullptr, nullptr, 0);
    reduce_ln_ln<<<B64, 256>>>(part, ln_ca_g, ln_ca_b, x2, glu_ln0_g, glu_ln0_b, x3, z1);

    // 7. GLU fc0/fc1 + side copy [C3,C4)
    wmma_small<<<dim3(GDIM / 128, SPLITS, 2 + 1), 256>>>(
        z1, glu_fc0, glu_fc1, glu_fc1, part, GDIM, EMB, 2,
        stsrc, stdst, C3, C4, nullptr, nullptr, 0);
    reduce_gelu_ln<<<B64, 256>>>(part, glu_ln1_g, glu_ln1_b, gln);

    // 8. fc2 + side copy [C4,end)
    wmma_small<<<dim3(EMB / 128, SPLITS, 1 + 1), 256>>>(
        gln, glu_fc2, glu_fc2, glu_fc2, part, EMB, GDIM, 1,
        stsrc, stdst, C4, N4T, nullptr, nullptr, 0);

    // 9. final: residual add + token-row scatter (after all copy chunks)
    reduce_add_scatter<<<(3 * B64 * EMB) / 256, 256>>>(part, x3, out_x, kvnew, out_state, tokp);
}

// round 14
// speedup vs baseline: 1.5920x; 1.0300x over previous
#include <cuda_runtime.h>
#include <cuda_fp16.h>
#include <mma.h>
#include <math.h>
#include <stdint.h>

using namespace nvcuda;

#define B64   64
#define EMB   2048
#define GDIM  4096
#define TENC  64
#define SKV   256
#define NH    32
#define HC    64

// ---------------- scratch ----------------
__device__ float g_x1[B64*EMB];
__device__ float g_q[B64*EMB];
__device__ float g_kvnew[2*B64*EMB];
__device__ float g_attnout[B64*EMB];
__device__ float g_x2[B64*EMB];
__device__ float g_y1[B64*EMB];
__device__ float g_x3[B64*EMB];
__device__ float g_z1[B64*EMB];
__device__ float g_gln[B64*GDIM];
__device__ float g_partial[3*16*B64*EMB > 2*8*B64*GDIM ? 3*16*B64*EMB : 2*8*B64*GDIM];
__device__ float g_vpart[NH*4*HC*B64];
__device__ __half g_ench[B64*TENC*EMB];
__device__ __half g_qk[B64*NH*EMB];
__device__ __half g_ctx[B64*NH*EMB];

__device__ __forceinline__ uint2 pack4h(float4 v) {
    __half2 h0 = __floats2half2_rn(v.x, v.y);
    __half2 h1 = __floats2half2_rn(v.z, v.w);
    uint2 u;
    u.x = *(uint32_t*)&h0;
    u.y = *(uint32_t*)&h1;
    return u;
}

// ---------------- layernorm ----------------
__global__ void ln_kernel(const float* __restrict__ in, const float* __restrict__ g,
                          const float* __restrict__ b, const float* __restrict__ res,
                          float* __restrict__ out, int W) {
    int row = blockIdx.x;
    const float* x = in + (long)row * W;
    float s = 0.f, ss = 0.f;
    for (int i = threadIdx.x; i < W; i += blockDim.x) { float v = x[i]; s += v; ss += v * v; }
    __shared__ float rs[32], rss[32];
    for (int o = 16; o; o >>= 1) { s += __shfl_down_sync(0xffffffffu, s, o); ss += __shfl_down_sync(0xffffffffu, ss, o); }
    int wid = threadIdx.x >> 5, lid = threadIdx.x & 31;
    if (!lid) { rs[wid] = s; rss[wid] = ss; }
    __syncthreads();
    if (threadIdx.x == 0) {
        float S = 0.f, SS = 0.f;
        int nw = blockDim.x >> 5;
        for (int i = 0; i < nw; i++) { S += rs[i]; SS += rss[i]; }
        rs[0] = S; rss[0] = SS;
    }
    __syncthreads();
    float m    = rs[0] / (float)W;
    float var  = rss[0] / (float)W - m * m;
    float rstd = rsqrtf(var + 1e-5f);
    float* o = out + (long)row * W;
    const float* r = res ? res + (long)row * W : nullptr;
    for (int i = threadIdx.x; i < W; i += blockDim.x) {
        float v = (x[i] - m) * rstd * g[i] + b[i];
        o[i] = r ? (r[i] + v) : v;
    }
}

// ---------------- small GEMM with side-work planes ----------------
// splits = gridDim.y. blockIdx.z < nW: compute. z==nW: copy [cb,ce). z==nW+1: cvt [0,vn).
__global__ __launch_bounds__(256) void wmma_small(
    const float* __restrict__ A, const float* __restrict__ Wa,
    const float* __restrict__ Wb, const float* __restrict__ Wc,
    float* __restrict__ part, int N, int K, int nW,
    const float4* __restrict__ csrc, float4* __restrict__ cdst, long cb, long ce,
    const float4* __restrict__ vsrc, uint2* __restrict__ vdst, long vn) {
    int zw = blockIdx.z;
    if (zw >= nW) {
        int role = zw - nW;
        long nb = (long)gridDim.x * gridDim.y;
        long sid = (long)blockIdx.y * gridDim.x + blockIdx.x;
        long stride = nb * blockDim.x;
        if (role == 0) {
            for (long i = cb + sid * blockDim.x + threadIdx.x; i < ce; i += stride)
                cdst[i] = csrc[i];
        } else {
            for (long i = sid * blockDim.x + threadIdx.x; i < vn; i += stride)
                vdst[i] = pack4h(vsrc[i]);
        }
        return;
    }
    int nt = blockIdx.x, s = blockIdx.y, w = zw;
    int nS = gridDim.y;
    const float* W = (w == 0) ? Wa : ((w == 1) ? Wb : Wc);
    int Ks = K / nS;
    int k0 = s * Ks;
    int n0 = nt * 128;
    __shared__ __align__(16) __half As[2][64][40];
    __shared__ __align__(16) __half Bs[2][32][136];
    int tid = threadIdx.x;
    int warp = tid >> 5;
    int wm = warp >> 1;
    int wn = warp & 1;

    wmma::fragment<wmma::accumulator, 16, 16, 16, float> c[4];
    #pragma unroll
    for (int j = 0; j < 4; j++) wmma::fill_fragment(c[j], 0.f);

    float4 ra[2], rb[4];
    int ar[2], ac[2], br[4], bc[4];
    #pragma unroll
    for (int u = 0; u < 2; u++) {
        int idx = tid + u * 256;
        ar[u] = idx >> 3;  ac[u] = (idx & 7) * 4;
    }
    #pragma unroll
    for (int u = 0; u < 4; u++) {
        int idx = tid + u * 256;
        br[u] = idx >> 5;  bc[u] = (idx & 31) * 4;
    }
    auto loadG = [&](int kt) {
        #pragma unroll
        for (int u = 0; u < 2; u++)
            ra[u] = *(const float4*)(A + (long)ar[u] * K + k0 + kt + ac[u]);
        #pragma unroll
        for (int u = 0; u < 4; u++)
            rb[u] = *(const float4*)(W + (long)(k0 + kt + br[u]) * N + n0 + bc[u]);
    };
    auto storeS = [&](int buf) {
        #pragma unroll
        for (int u = 0; u < 2; u++)
            *(uint2*)&As[buf][ar[u]][ac[u]] = pack4h(ra[u]);
        #pragma unroll
        for (int u = 0; u < 4; u++)
            *(uint2*)&Bs[buf][br[u]][bc[u]] = pack4h(rb[u]);
    };

    loadG(0);
    storeS(0);
    __syncthreads();
    int buf = 0;

    for (int kt = 0; kt < Ks; kt += 32) {
        int nxt = kt + 32;
        if (nxt < Ks) loadG(nxt);
        #pragma unroll
        for (int k16 = 0; k16 < 32; k16 += 16) {
            wmma::fragment<wmma::matrix_a, 16, 16, 16, __half, wmma::row_major> a;
            wmma::load_matrix_sync(a, &As[buf][wm * 16][k16], 40);
            #pragma unroll
            for (int j = 0; j < 4; j++) {
                wmma::fragment<wmma::matrix_b, 16, 16, 16, __half, wmma::row_major> b;
                wmma::load_matrix_sync(b, &Bs[buf][k16][wn * 64 + j * 16], 136);
                wmma::mma_sync(c[j], a, b, c[j]);
            }
        }
        if (nxt < Ks) storeS(buf ^ 1);
        __syncthreads();
        buf ^= 1;
    }
    float* P = part + (long)(w * nS + s) * 64 * N;
    #pragma unroll
    for (int j = 0; j < 4; j++)
        wmma::store_matrix_sync(P + (long)(wm * 16) * N + n0 + wn * 64 + j * 16,
                                c[j], N, wmma::mem_row_major);
}

// ---------------- qk_gemm (reads q split-K partials directly) ----------------
template <int NS>
__global__ __launch_bounds__(256) void qk_gemm(const float* __restrict__ part,
                                               const float* __restrict__ Wk,
                                               __half* __restrict__ qk) {
    int e0 = blockIdx.x * 128, h = blockIdx.y;
    __shared__ __align__(16) __half As[64][72];
    __shared__ __align__(16) __half Bs[128][72];
    __shared__ float patch[8][16][20];
    int tid = threadIdx.x;
    int warp = tid >> 5, lane = tid & 31;
    int wm = warp >> 1;
    int wn = warp & 1;

    #pragma unroll
    for (int u = 0; u < 4; u++) {
        int idx = tid + u * 256;
        int b = idx >> 4, c4 = (idx & 15) * 4;
        float4 acc = make_float4(0.f, 0.f, 0.f, 0.f);
        #pragma unroll
        for (int k = 0; k < NS; k++) {
            float4 v = *(const float4*)(part + (long)k * B64 * EMB + (long)b * EMB + h * 64 + c4);
            acc.x += v.x; acc.y += v.y; acc.z += v.z; acc.w += v.w;
        }
        *(uint2*)&As[b][c4] = pack4h(acc);
    }
    #pragma unroll
    for (int u = 0; u < 8; u++) {
        int idx = tid + u * 256;
        int e = idx >> 4, c4 = (idx & 15) * 4;
        float4 v = *(const float4*)(Wk + (long)(e0 + e) * EMB + h * 64 + c4);
        *(uint2*)&Bs[e][c4] = pack4h(v);
    }
    __syncthreads();

    wmma::fragment<wmma::accumulator, 16, 16, 16, float> c[4];
    #pragma unroll
    for (int j = 0; j < 4; j++) wmma::fill_fragment(c[j], 0.f);
    #pragma unroll
    for (int k16 = 0; k16 < 64; k16 += 16) {
        wmma::fragment<wmma::matrix_a, 16, 16, 16, __half, wmma::row_major> a;
        wmma::load_matrix_sync(a, &As[wm * 16][k16], 72);
        #pragma unroll
        for (int j = 0; j < 4; j++) {
            wmma::fragment<wmma::matrix_b, 16, 16, 16, __half, wmma::col_major> b;
            wmma::load_matrix_sync(b, &Bs[wn * 64 + j * 16][k16], 72);
            wmma::mma_sync(c[j], a, b, c[j]);
        }
    }
    #pragma unroll
    for (int j = 0; j < 4; j++) {
        wmma::store_matrix_sync(&patch[warp][0][0], c[j], 20, wmma::mem_row_major);
        __syncwarp();
        int r = lane >> 1, c0 = (lane & 1) * 8;
        float* p = &patch[warp][r][c0];
        __half2 h0 = __floats2half2_rn(p[0], p[1]);
        __half2 h1 = __floats2half2_rn(p[2], p[3]);
        __half2 h2 = __floats2half2_rn(p[4], p[5]);
        __half2 h3 = __floats2half2_rn(p[6], p[7]);
        uint4 pk = make_uint4(*(uint32_t*)&h0, *(uint32_t*)&h1, *(uint32_t*)&h2, *(uint32_t*)&h3);
        int b = wm * 16 + r;
        long off = ((long)b * NH + h) * EMB + e0 + wn * 64 + j * 16 + c0;
        *(uint4*)(qk + off) = pk;
        __syncwarp();
    }
}

// ---------------- cross_attn ----------------
__global__ __launch_bounds__(256) void cross_attn(const __half* __restrict__ qk,
                                                  const __half* __restrict__ ench,
                                                  __half* __restrict__ ctx) {
    int b = blockIdx.x;
    int tid = threadIdx.x;
    int warp = tid >> 5, lane = tid & 31;
    const __half* A = qk + (long)b * NH * EMB;
    const __half* E = ench + (long)b * TENC * EMB;
    __shared__ float sc[32][72];
    __shared__ __half wsh[32][72];
    __shared__ float patch[8][16][20];

    {
        int wm = warp >> 2, wn = warp & 3;
        wmma::fragment<wmma::accumulator, 16, 16, 16, float> acc;
        wmma::fill_fragment(acc, 0.f);
        for (int k16 = 0; k16 < EMB; k16 += 16) {
            wmma::fragment<wmma::matrix_a, 16, 16, 16, __half, wmma::row_major> a;
            wmma::fragment<wmma::matrix_b, 16, 16, 16, __half, wmma::col_major> bb;
            wmma::load_matrix_sync(a, A + (long)(wm * 16) * EMB + k16, EMB);
            wmma::load_matrix_sync(bb, E + (long)(wn * 16) * EMB + k16, EMB);
            wmma::mma_sync(acc, a, bb, acc);
        }
        wmma::store_matrix_sync(&sc[wm * 16][wn * 16], acc, 72, wmma::mem_row_major);
    }
    __syncthreads();

    if (tid < 32) {
        float mx = -1e30f;
        #pragma unroll
        for (int k = 0; k < TENC; k++) mx = fmaxf(mx, sc[tid][k] * 0.125f);
        float sum = 0.f;
        float ex[TENC];
        #pragma unroll
        for (int k = 0; k < TENC; k++) { ex[k] = expf(sc[tid][k] * 0.125f - mx); sum += ex[k]; }
        float inv = 1.f / sum;
        #pragma unroll
        for (int k = 0; k < TENC; k++) wsh[tid][k] = __float2half(ex[k] * inv);
    }
    __syncthreads();

    {
        int wm = warp >> 2, wn = warp & 3;
        for (int nt = wn; nt < 128; nt += 4) {
            wmma::fragment<wmma::accumulator, 16, 16, 16, float> acc;
            wmma::fill_fragment(acc, 0.f);
            #pragma unroll
            for (int kk = 0; kk < TENC; kk += 16) {
                wmma::fragment<wmma::matrix_a, 16, 16, 16, __half, wmma::row_major> a;
                wmma::fragment<wmma::matrix_b, 16, 16, 16, __half, wmma::row_major> bb;
                wmma::load_matrix_sync(a, &wsh[wm * 16][kk], 72);
                wmma::load_matrix_sync(bb, E + (long)kk * EMB + nt * 16, EMB);
                wmma::mma_sync(acc, a, bb, acc);
            }
            wmma::store_matrix_sync(&patch[warp][0][0], acc, 20, wmma::mem_row_major);
            __syncwarp();
            int r = lane >> 1, c0 = (lane & 1) * 8;
            float* p = &patch[warp][r][c0];
            __half2 h0 = __floats2half2_rn(p[0], p[1]);
            __half2 h1 = __floats2half2_rn(p[2], p[3]);
            __half2 h2 = __floats2half2_rn(p[4], p[5]);
            __half2 h3 = __floats2half2_rn(p[6], p[7]);
            uint4 pk = make_uint4(*(uint32_t*)&h0, *(uint32_t*)&h1, *(uint32_t*)&h2, *(uint32_t*)&h3);
            int h = wm * 16 + r;
            long off = ((long)b * NH + h) * EMB + nt * 16 + c0;
            *(uint4*)(ctx + off) = pk;
            __syncwarp();
        }
    }
}

// ---------------- outv_gemm ----------------
__global__ __launch_bounds__(256) void outv_gemm(const __half* __restrict__ ctx,
                                                 const float* __restrict__ Wv,
                                                 float* __restrict__ part) {
    int h = blockIdx.x, s = blockIdx.y;
    int k0 = s * 512;
    __shared__ __align__(16) __half Bs[32][72];
    int tid = threadIdx.x;
    int warp = tid >> 5;
    int wm = warp >> 1;
    int wn = warp & 1;
    const __half* A = ctx + (long)h * EMB + k0;

    wmma::fragment<wmma::accumulator, 16, 16, 16, float> c[2];
    wmma::fill_fragment(c[0], 0.f);
    wmma::fill_fragment(c[1], 0.f);

    for (int kt = 0; kt < 512; kt += 32) {
        #pragma unroll
        for (int u = 0; u < 2; u++) {
            int idx = tid + u * 256;
            int e = idx >> 4, c4 = (idx & 15) * 4;
            float4 v = *(const float4*)(Wv + (long)(k0 + kt + e) * EMB + h * 64 + c4);
            *(uint2*)&Bs[e][c4] = pack4h(v);
        }
        __syncthreads();
        #pragma unroll
        for (int k16 = 0; k16 < 32; k16 += 16) {
            wmma::fragment<wmma::matrix_a, 16, 16, 16, __half, wmma::row_major> a;
            wmma::load_matrix_sync(a, A + (long)(wm * 16) * (NH * EMB) + kt + k16, NH * EMB);
            #pragma unroll
            for (int j = 0; j < 2; j++) {
                wmma::fragment<wmma::matrix_b, 16, 16, 16, __half, wmma::row_major> bb;
                wmma::load_matrix_sync(bb, &Bs[k16][wn * 32 + j * 16], 72);
                wmma::mma_sync(c[j], a, bb, c[j]);
            }
        }
        __syncthreads();
    }
    float* P = part + (long)(h * 4 + s) * 4096;
    #pragma unroll
    for (int j = 0; j < 2; j++)
        wmma::store_matrix_sync(P + (long)(wm * 16) * 64 + wn * 32 + j * 16,
                                c[j], 64, wmma::mem_row_major);
}

__global__ void reduce_outv(const float* __restrict__ part, float* __restrict__ attnout) {
    int idx = blockIdx.x * blockDim.x + threadIdx.x;
    if (idx >= B64 * EMB) return;
    int b = idx >> 11, r = idx & (EMB - 1);
    int h = r >> 6, cc = r & 63;
    float s = 0.f;
    #pragma unroll
    for (int k = 0; k < 4; k++) s += part[(long)(h * 4 + k) * 4096 + b * 64 + cc];
    attnout[idx] = s;
}

// ---------------- fused epilogues ----------------
template <int NS>
__global__ void reduce_qkv(const float* __restrict__ part, float* __restrict__ q,
                           float* __restrict__ kvnew) {
    int idx = blockIdx.x * blockDim.x + threadIdx.x;
    if (idx >= 3 * B64 * EMB) return;
    int w = idx / (B64 * EMB);
    int rem = idx - w * B64 * EMB;
    float s = 0.f;
    #pragma unroll
    for (int k = 0; k < NS; k++) s += part[(long)(w * NS + k) * B64 * EMB + rem];
    if (w == 0) q[rem] = s;
    else kvnew[(long)(w - 1) * B64 * EMB + rem] = s;
}

template <int NS>
__global__ void reduce_ln_ln(const float* __restrict__ part,
                             const float* __restrict__ g1, const float* __restrict__ b1,
                             const float* __restrict__ res,
                             const float* __restrict__ g2, const float* __restrict__ b2,
                             float* __restrict__ xout, float* __restrict__ yout) {
    const int W = EMB;
    __shared__ float buf[EMB];
    __shared__ float rs[32], rss[32];
    int row = blockIdx.x;
    float s = 0.f, ss = 0.f;
    for (int i = threadIdx.x; i < W; i += blockDim.x) {
        float v = 0.f;
        #pragma unroll
        for (int k = 0; k < NS; k++) v += part[(long)k * B64 * W + (long)row * W + i];
        buf[i] = v; s += v; ss += v * v;
    }
    int wid = threadIdx.x >> 5, lid = threadIdx.x & 31;
    for (int o = 16; o; o >>= 1) { s += __shfl_down_sync(0xffffffffu, s, o); ss += __shfl_down_sync(0xffffffffu, ss, o); }
    if (!lid) { rs[wid] = s; rss[wid] = ss; }
    __syncthreads();
    if (threadIdx.x == 0) {
        float S = 0.f, SS = 0.f;
        for (int i = 0; i < (int)(blockDim.x >> 5); i++) { S += rs[i]; SS += rss[i]; }
        rs[0] = S; rss[0] = SS;
    }
    __syncthreads();
    float m    = rs[0] / (float)W;
    float var  = rss[0] / (float)W - m * m;
    float rstd = rsqrtf(var + 1e-5f);
    __syncthreads();
    float s2 = 0.f, ss2 = 0.f;
    const float* r = res + (long)row * W;
    float* xo = xout + (long)row * W;
    for (int i = threadIdx.x; i < W; i += blockDim.x) {
        float t = r[i] + (buf[i] - m) * rstd * g1[i] + b1[i];
        buf[i] = t; xo[i] = t; s2 += t; ss2 += t * t;
    }
    for (int o = 16; o; o >>= 1) { s2 += __shfl_down_sync(0xffffffffu, s2, o); ss2 += __shfl_down_sync(0xffffffffu, ss2, o); }
    if (!lid) { rs[wid] = s2; rss[wid] = ss2; }
    __syncthreads();
    if (threadIdx.x == 0) {
        float S = 0.f, SS = 0.f;
        for (int i = 0; i < (int)(blockDim.x >> 5); i++) { S += rs[i]; SS += rss[i]; }
        rs[0] = S; rss[0] = SS;
    }
    __syncthreads();
    float m2    = rs[0] / (float)W;
    float var2  = rss[0] / (float)W - m2 * m2;
    float rstd2 = rsqrtf(var2 + 1e-5f);
    float* yo = yout + (long)row * W;
    for (int i = threadIdx.x; i < W; i += blockDim.x)
        yo[i] = (buf[i] - m2) * rstd2 * g2[i] + b2[i];
}

template <int NS>
__global__ void reduce_gelu_ln(const float* __restrict__ part,
                               const float* __restrict__ g, const float* __restrict__ b,
                               float* __restrict__ out) {
    const int W = GDIM;
    __shared__ float buf[GDIM];
    __shared__ float rs[32], rss[32];
    int row = blockIdx.x;
    float s = 0.f, ss = 0.f;
    for (int i = threadIdx.x; i < W; i += blockDim.x) {
        float a = 0.f, c = 0.f;
        #pragma unroll
        for (int k = 0; k < NS; k++) {
            a += part[(long)k * B64 * W + (long)row * W + i];
            c += part[(long)(NS + k) * B64 * W + (long)row * W + i];
        }
        float gl = 0.5f * a * (1.f + erff(a * 0.70710678118654752f));
        float v = gl * c;
        buf[i] = v; s += v; ss += v * v;
    }
    int wid = threadIdx.x >> 5, lid = threadIdx.x & 31;
    for (int o = 16; o; o >>= 1) { s += __shfl_down_sync(0xffffffffu, s, o); ss += __shfl_down_sync(0xffffffffu, ss, o); }
    if (!lid) { rs[wid] = s; rss[wid] = ss; }
    __syncthreads();
    if (threadIdx.x == 0) {
        float S = 0.f, SS = 0.f;
        for (int i = 0; i < (int)(blockDim.x >> 5); i++) { S += rs[i]; SS += rss[i]; }
        rs[0] = S; rss[0] = SS;
    }
    __syncthreads();
    float m    = rs[0] / (float)W;
    float var  = rss[0] / (float)W - m * m;
    float rstd = rsqrtf(var + 1e-5f);
    float* o = out + (long)row * W;
    for (int i = threadIdx.x; i < W; i += blockDim.x)
        o[i] = (buf[i] - m) * rstd * g[i] + b[i];
}

template <int NS>
__global__ void reduce_add_scatter(const float* __restrict__ part, const float* __restrict__ res,
                                   float* __restrict__ out_x, const float* __restrict__ kvnew,
                                   float* __restrict__ outstate, const int* __restrict__ tokp) {
    int idx = blockIdx.x * blockDim.x + threadIdx.x;
    if (idx < B64 * EMB) {
        float s = 0.f;
        #pragma unroll
        for (int k = 0; k < NS; k++) s += part[(long)k * B64 * EMB + idx];
        out_x[idx] = res[idx] + s;
    } else {
        int j = idx - B64 * EMB;
        if (j < 2 * B64 * EMB) {
            int tok = *tokp;
            int bb = j >> 11, e = j & (EMB - 1);
            outstate[((long)bb * SKV + tok) * EMB + e] = kvnew[j];
        }
    }
}

// ---------------- self-attention: 256 threads, split-j V accumulation --------------
__global__ __launch_bounds__(256) void self_attn(
    const float* __restrict__ Q, const float* __restrict__ astate,
    const float* __restrict__ kvnew, float* __restrict__ O,
    const int* __restrict__ tokp) {
    int b = blockIdx.x, h = blockIdx.y;
    int tok = *tokp;
    int L = tok + 1;
    __shared__ float qsh[HC];
    __shared__ float sc[SKV];
    __shared__ float red[256];
    __shared__ float vred[4][HC];
    int tid = threadIdx.x;
    if (tid < HC) qsh[tid] = Q[(long)b * EMB + h * HC + tid];
    __syncthreads();

    int warp = tid >> 5, lane = tid & 31;
    for (int j = warp; j < L; j += 8) {
        const float* kp = (j == tok)
            ? kvnew + (long)b * EMB + h * HC
            : astate + ((long)b * SKV + j) * EMB + h * HC;
        float d = qsh[lane] * kp[lane] + qsh[lane + 32] * kp[lane + 32];
        for (int o = 16; o; o >>= 1) d += __shfl_down_sync(0xffffffffu, d, o);
        if (!lane) sc[j] = d * 0.125f;
    }
    __syncthreads();

    float mx = -1e30f;
    for (int j = tid; j < L; j += 256) mx = fmaxf(mx, sc[j]);
    red[tid] = mx; __syncthreads();
    for (int st = 128; st; st >>= 1) { if (tid < st) red[tid] = fmaxf(red[tid], red[tid + st]); __syncthreads(); }
    mx = red[0];
    __syncthreads();

    float sum = 0.f;
    for (int j = tid; j < L; j += 256) { float e = expf(sc[j] - mx); sc[j] = e; sum += e; }
    red[tid] = sum; __syncthreads();
    for (int st = 128; st; st >>= 1) { if (tid < st) red[tid] += red[tid + st]; __syncthreads(); }
    float inv = 1.f / red[0];
    __syncthreads();

    // V accumulation: 4 j-groups x 64 channels
    {
        int g = tid >> 6, cc = tid & 63;
        float acc = 0.f;
        const float* vbase = astate + ((long)(B64 + b) * SKV) * EMB + h * HC + cc;
        for (int j = g; j < L; j += 4) {
            float v = (j == tok) ? kvnew[(long)(B64 + b) * EMB + h * HC + cc]
                                 : vbase[(long)j * EMB];
            acc += sc[j] * v;
        }
        vred[g][cc] = acc;
    }
    __syncthreads();
    if (tid < HC) {
        float acc = vred[0][tid] + vred[1][tid] + vred[2][tid] + vred[3][tid];
        O[(long)b * EMB + h * HC + tid] = acc * inv;
    }
}

// ---------------- host orchestration ----------------
extern "C" void kernel_launch(void* const* d_in, const int* in_sizes, int n_in,
                              void* d_out, int out_size) {
    const float* dec        = (const float*)d_in[0];
    const float* enc        = (const float*)d_in[1];
    const float* astate     = (const float*)d_in[2];
    const int*   tokp       = (const int*)d_in[4];
    const float* ln_pre_sa_g = (const float*)d_in[5];
    const float* ln_pre_sa_b = (const float*)d_in[6];
    const float* ln_sa_g     = (const float*)d_in[7];
    const float* ln_sa_b     = (const float*)d_in[8];
    const float* ln_pre_ca_g = (const float*)d_in[9];
    const float* ln_pre_ca_b = (const float*)d_in[10];
    const float* ln_ca_g     = (const float*)d_in[11];
    const float* ln_ca_b     = (const float*)d_in[12];
    const float* sa_wq = (const float*)d_in[13];
    const float* sa_wk = (const float*)d_in[14];
    const float* sa_wv = (const float*)d_in[15];
    const float* sa_wo = (const float*)d_in[16];
    const float* ca_wq = (const float*)d_in[17];
    const float* ca_wk = (const float*)d_in[18];
    const float* ca_wv = (const float*)d_in[19];
    const float* ca_wo = (const float*)d_in[20];
    const float* glu_ln0_g = (const float*)d_in[21];
    const float* glu_ln0_b = (const float*)d_in[22];
    const float* glu_fc0   = (const float*)d_in[23];
    const float* glu_fc1   = (const float*)d_in[24];
    const float* glu_ln1_g = (const float*)d_in[25];
    const float* glu_ln1_b = (const float*)d_in[26];
    const float* glu_fc2   = (const float*)d_in[27];

    float* out       = (float*)d_out;
    float* out_x     = out;
    float* out_state = out + (long)B64 * EMB;

    float *x1, *q, *kvnew, *attnout, *x2, *y1, *x3, *z1, *gln, *part, *vpart;
    __half *ench, *qkh, *ctxh;
    cudaGetSymbolAddress((void**)&x1, g_x1);
    cudaGetSymbolAddress((void**)&q, g_q);
    cudaGetSymbolAddress((void**)&kvnew, g_kvnew);
    cudaGetSymbolAddress((void**)&attnout, g_attnout);
    cudaGetSymbolAddress((void**)&x2, g_x2);
    cudaGetSymbolAddress((void**)&y1, g_y1);
    cudaGetSymbolAddress((void**)&x3, g_x3);
    cudaGetSymbolAddress((void**)&z1, g_z1);
    cudaGetSymbolAddress((void**)&gln, g_gln);
    cudaGetSymbolAddress((void**)&part, g_partial);
    cudaGetSymbolAddress((void**)&vpart, g_vpart);
    cudaGetSymbolAddress((void**)&ench, g_ench);
    cudaGetSymbolAddress((void**)&qkh, g_qk);
    cudaGetSymbolAddress((void**)&ctxh, g_ctx);

    const float4* stsrc = (const float4*)astate;
    float4* stdst = (float4*)out_state;
    const long N4T = (long)2 * B64 * SKV * EMB / 4;
    const long NE  = (long)B64 * TENC * EMB / 4;
    const long C0 = 2000000, C1 = 4500000, C2 = 7000000, C3 = 9500000, C4 = 14000000;

    // 1. x1 = LN(decoder_state)
    ln_kernel<<<B64, 256>>>(dec, ln_pre_sa_g, ln_pre_sa_b, nullptr, x1, EMB);

    // 2. qkv projections (16 splits) + side: copy [0,C0) + enc convert
    wmma_small<<<dim3(EMB / 128, 16, 3 + 2), 256>>>(
        x1, sa_wq, sa_wk, sa_wv, part, EMB, EMB, 3,
        stsrc, stdst, 0, C0, (const float4*)enc, (uint2*)ench, NE);
    reduce_qkv<16><<<(3 * B64 * EMB) / 256, 256>>>(part, q, kvnew);

    // 3. self-attention
    self_attn<<<dim3(B64, NH), 256>>>(q, astate, kvnew, attnout, tokp);

    // 4. sa out-proj (16 splits) + side copy [C0,C1)
    wmma_small<<<dim3(EMB / 128, 16, 1 + 1), 256>>>(
        attnout, sa_wo, sa_wo, sa_wo, part, EMB, EMB, 1,
        stsrc, stdst, C0, C1, nullptr, nullptr, 0);
    reduce_ln_ln<16><<<B64, 512>>>(part, ln_sa_g, ln_sa_b, dec, ln_pre_ca_g, ln_pre_ca_b, x2, y1);

    // 5. ca_wq (16 splits) + side copy [C1,C2); qk_gemm reads partials
    wmma_small<<<dim3(EMB / 128, 16, 1 + 1), 256>>>(
        y1, ca_wq, ca_wq, ca_wq, part, EMB, EMB, 1,
        stsrc, stdst, C1, C2, nullptr, nullptr, 0);
    qk_gemm<16><<<dim3(16, NH), 256>>>(part, ca_wk, qkh);
    cross_attn<<<B64, 256>>>(qkh, ench, ctxh);
    outv_gemm<<<dim3(NH, 4), 256>>>(ctxh, ca_wv, vpart);
    reduce_outv<<<(B64 * EMB) / 256, 256>>>(vpart, attnout);

    // 6. ca out-proj (16 splits) + side copy [C2,C3)
    wmma_small<<<dim3(EMB / 128, 16, 1 + 1), 256>>>(
        attnout, ca_wo, ca_wo, ca_wo, part, EMB, EMB, 1,
        stsrc, stdst, C2, C3, nullptr, nullptr, 0);
    reduce_ln_ln<16><<<B64, 512>>>(part, ln_ca_g, ln_ca_b, x2, glu_ln0_g, glu_ln0_b, x3, z1);

    // 7. GLU fc0/fc1 (8 splits) + side copy [C3,C4)
    wmma_small<<<dim3(GDIM / 128, 8, 2 + 1), 256>>>(
        z1, glu_fc0, glu_fc1, glu_fc1, part, GDIM, EMB, 2,
        stsrc, stdst, C3, C4, nullptr, nullptr, 0);
    reduce_gelu_ln<8><<<B64, 512>>>(part, glu_ln1_g, glu_ln1_b, gln);

    // 8. fc2 (16 splits) + side copy [C4,end)
    wmma_small<<<dim3(EMB / 128, 16, 1 + 1), 256>>>(
        gln, glu_fc2, glu_fc2, glu_fc2, part, EMB, GDIM, 1,
        stsrc, stdst, C4, N4T, nullptr, nullptr, 0);

    // 9. final: residual add + token-row scatter
    reduce_add_scatter<16><<<(3 * B64 * EMB) / 256, 256>>>(part, x3, out_x, kvnew, out_state, tokp);
}

// round 15
// speedup vs baseline: 1.6533x; 1.0385x over previous
#include <cuda_runtime.h>
#include <cuda_fp16.h>
#include <mma.h>
#include <math.h>
#include <stdint.h>

using namespace nvcuda;

#define B64   64
#define EMB   2048
#define GDIM  4096
#define TENC  64
#define SKV   256
#define NH    32
#define HC    64

// ---------------- scratch ----------------
__device__ float g_x1[B64*EMB];
__device__ float g_attnout[B64*EMB];
__device__ float g_x2[B64*EMB];
__device__ float g_y1[B64*EMB];
__device__ float g_x3[B64*EMB];
__device__ float g_z1[B64*EMB];
__device__ float g_gln[B64*GDIM];
__device__ float g_partial[2*8*B64*GDIM];        // max user: fc0/fc1 (16 x 64 x 4096)
__device__ float g_kvpart[2*16*B64*EMB];         // k/v split-K partials (live till end)
__device__ float g_vpart[NH*4*HC*B64];
__device__ __half g_ench[B64*TENC*EMB];
__device__ __half g_qk[B64*NH*EMB];
__device__ __half g_ctx[B64*NH*EMB];

__device__ __forceinline__ uint2 pack4h(float4 v) {
    __half2 h0 = __floats2half2_rn(v.x, v.y);
    __half2 h1 = __floats2half2_rn(v.z, v.w);
    uint2 u;
    u.x = *(uint32_t*)&h0;
    u.y = *(uint32_t*)&h1;
    return u;
}

// ---------------- layernorm ----------------
__global__ void ln_kernel(const float* __restrict__ in, const float* __restrict__ g,
                          const float* __restrict__ b, const float* __restrict__ res,
                          float* __restrict__ out, int W) {
    int row = blockIdx.x;
    const float* x = in + (long)row * W;
    float s = 0.f, ss = 0.f;
    for (int i = threadIdx.x; i < W; i += blockDim.x) { float v = x[i]; s += v; ss += v * v; }
    __shared__ float rs[32], rss[32];
    for (int o = 16; o; o >>= 1) { s += __shfl_down_sync(0xffffffffu, s, o); ss += __shfl_down_sync(0xffffffffu, ss, o); }
    int wid = threadIdx.x >> 5, lid = threadIdx.x & 31;
    if (!lid) { rs[wid] = s; rss[wid] = ss; }
    __syncthreads();
    if (threadIdx.x == 0) {
        float S = 0.f, SS = 0.f;
        int nw = blockDim.x >> 5;
        for (int i = 0; i < nw; i++) { S += rs[i]; SS += rss[i]; }
        rs[0] = S; rss[0] = SS;
    }
    __syncthreads();
    float m    = rs[0] / (float)W;
    float var  = rss[0] / (float)W - m * m;
    float rstd = rsqrtf(var + 1e-5f);
    float* o = out + (long)row * W;
    const float* r = res ? res + (long)row * W : nullptr;
    for (int i = threadIdx.x; i < W; i += blockDim.x) {
        float v = (x[i] - m) * rstd * g[i] + b[i];
        o[i] = r ? (r[i] + v) : v;
    }
}

// ---------------- small GEMM with side-work planes ----------------
// splits = gridDim.y. z < nW: compute; z==nW: copy [cb,ce); z==nW+1: cvt [0,vn).
// partKV: if non-null, w>=1 partials go there at slot (w-1)*nS+s.
// vp: if non-null, A operand = sum of 4 vpart slices (attnout not yet materialized).
__global__ __launch_bounds__(256) void wmma_small(
    const float* __restrict__ A, const float* __restrict__ Wa,
    const float* __restrict__ Wb, const float* __restrict__ Wc,
    float* __restrict__ part, int N, int K, int nW,
    const float4* __restrict__ csrc, float4* __restrict__ cdst, long cb, long ce,
    const float4* __restrict__ vsrc, uint2* __restrict__ vdst, long vn,
    float* __restrict__ partKV, const float* __restrict__ vp) {
    int zw = blockIdx.z;
    if (zw >= nW) {
        int role = zw - nW;
        long nb = (long)gridDim.x * gridDim.y;
        long sid = (long)blockIdx.y * gridDim.x + blockIdx.x;
        long stride = nb * blockDim.x;
        if (role == 0) {
            for (long i = cb + sid * blockDim.x + threadIdx.x; i < ce; i += stride)
                cdst[i] = csrc[i];
        } else {
            for (long i = sid * blockDim.x + threadIdx.x; i < vn; i += stride)
                vdst[i] = pack4h(vsrc[i]);
        }
        return;
    }
    int nt = blockIdx.x, s = blockIdx.y, w = zw;
    int nS = gridDim.y;
    const float* W = (w == 0) ? Wa : ((w == 1) ? Wb : Wc);
    int Ks = K / nS;
    int k0 = s * Ks;
    int n0 = nt * 128;
    __shared__ __align__(16) __half As[2][64][40];
    __shared__ __align__(16) __half Bs[2][32][136];
    int tid = threadIdx.x;
    int warp = tid >> 5;
    int wm = warp >> 1;
    int wn = warp & 1;

    wmma::fragment<wmma::accumulator, 16, 16, 16, float> c[4];
    #pragma unroll
    for (int j = 0; j < 4; j++) wmma::fill_fragment(c[j], 0.f);

    float4 ra[2], rb[4];
    int ar[2], ac[2], br[4], bc[4];
    #pragma unroll
    for (int u = 0; u < 2; u++) {
        int idx = tid + u * 256;
        ar[u] = idx >> 3;  ac[u] = (idx & 7) * 4;
    }
    #pragma unroll
    for (int u = 0; u < 4; u++) {
        int idx = tid + u * 256;
        br[u] = idx >> 5;  bc[u] = (idx & 31) * 4;
    }
    auto loadG = [&](int kt) {
        if (vp) {
            #pragma unroll
            for (int u = 0; u < 2; u++) {
                int e = k0 + kt + ac[u];
                int hh = e >> 6, cc = e & 63;
                float4 acc = make_float4(0.f, 0.f, 0.f, 0.f);
                #pragma unroll
                for (int sv = 0; sv < 4; sv++) {
                    float4 v = *(const float4*)(vp + (long)(hh * 4 + sv) * 4096 + ar[u] * 64 + cc);
                    acc.x += v.x; acc.y += v.y; acc.z += v.z; acc.w += v.w;
                }
                ra[u] = acc;
            }
        } else {
            #pragma unroll
            for (int u = 0; u < 2; u++)
                ra[u] = *(const float4*)(A + (long)ar[u] * K + k0 + kt + ac[u]);
        }
        #pragma unroll
        for (int u = 0; u < 4; u++)
            rb[u] = *(const float4*)(W + (long)(k0 + kt + br[u]) * N + n0 + bc[u]);
    };
    auto storeS = [&](int buf) {
        #pragma unroll
        for (int u = 0; u < 2; u++)
            *(uint2*)&As[buf][ar[u]][ac[u]] = pack4h(ra[u]);
        #pragma unroll
        for (int u = 0; u < 4; u++)
            *(uint2*)&Bs[buf][br[u]][bc[u]] = pack4h(rb[u]);
    };

    loadG(0);
    storeS(0);
    __syncthreads();
    int buf = 0;

    for (int kt = 0; kt < Ks; kt += 32) {
        int nxt = kt + 32;
        if (nxt < Ks) loadG(nxt);
        #pragma unroll
        for (int k16 = 0; k16 < 32; k16 += 16) {
            wmma::fragment<wmma::matrix_a, 16, 16, 16, __half, wmma::row_major> a;
            wmma::load_matrix_sync(a, &As[buf][wm * 16][k16], 40);
            #pragma unroll
            for (int j = 0; j < 4; j++) {
                wmma::fragment<wmma::matrix_b, 16, 16, 16, __half, wmma::row_major> b;
                wmma::load_matrix_sync(b, &Bs[buf][k16][wn * 64 + j * 16], 136);
                wmma::mma_sync(c[j], a, b, c[j]);
            }
        }
        if (nxt < Ks) storeS(buf ^ 1);
        __syncthreads();
        buf ^= 1;
    }
    float* P = (partKV && w >= 1)
        ? partKV + (long)((w - 1) * nS + s) * 64 * N
        : part + (long)(w * nS + s) * 64 * N;
    #pragma unroll
    for (int j = 0; j < 4; j++)
        wmma::store_matrix_sync(P + (long)(wm * 16) * N + n0 + wn * 64 + j * 16,
                                c[j], N, wmma::mem_row_major);
}

// ---------------- qk_gemm (reads q split-K partials directly) ----------------
template <int NS>
__global__ __launch_bounds__(256) void qk_gemm(const float* __restrict__ part,
                                               const float* __restrict__ Wk,
                                               __half* __restrict__ qk) {
    int e0 = blockIdx.x * 128, h = blockIdx.y;
    __shared__ __align__(16) __half As[64][72];
    __shared__ __align__(16) __half Bs[128][72];
    __shared__ float patch[8][16][20];
    int tid = threadIdx.x;
    int warp = tid >> 5, lane = tid & 31;
    int wm = warp >> 1;
    int wn = warp & 1;

    #pragma unroll
    for (int u = 0; u < 4; u++) {
        int idx = tid + u * 256;
        int b = idx >> 4, c4 = (idx & 15) * 4;
        float4 acc = make_float4(0.f, 0.f, 0.f, 0.f);
        #pragma unroll
        for (int k = 0; k < NS; k++) {
            float4 v = *(const float4*)(part + (long)k * B64 * EMB + (long)b * EMB + h * 64 + c4);
            acc.x += v.x; acc.y += v.y; acc.z += v.z; acc.w += v.w;
        }
        *(uint2*)&As[b][c4] = pack4h(acc);
    }
    #pragma unroll
    for (int u = 0; u < 8; u++) {
        int idx = tid + u * 256;
        int e = idx >> 4, c4 = (idx & 15) * 4;
        float4 v = *(const float4*)(Wk + (long)(e0 + e) * EMB + h * 64 + c4);
        *(uint2*)&Bs[e][c4] = pack4h(v);
    }
    __syncthreads();

    wmma::fragment<wmma::accumulator, 16, 16, 16, float> c[4];
    #pragma unroll
    for (int j = 0; j < 4; j++) wmma::fill_fragment(c[j], 0.f);
    #pragma unroll
    for (int k16 = 0; k16 < 64; k16 += 16) {
        wmma::fragment<wmma::matrix_a, 16, 16, 16, __half, wmma::row_major> a;
        wmma::load_matrix_sync(a, &As[wm * 16][k16], 72);
        #pragma unroll
        for (int j = 0; j < 4; j++) {
            wmma::fragment<wmma::matrix_b, 16, 16, 16, __half, wmma::col_major> b;
            wmma::load_matrix_sync(b, &Bs[wn * 64 + j * 16][k16], 72);
            wmma::mma_sync(c[j], a, b, c[j]);
        }
    }
    #pragma unroll
    for (int j = 0; j < 4; j++) {
        wmma::store_matrix_sync(&patch[warp][0][0], c[j], 20, wmma::mem_row_major);
        __syncwarp();
        int r = lane >> 1, c0 = (lane & 1) * 8;
        float* p = &patch[warp][r][c0];
        __half2 h0 = __floats2half2_rn(p[0], p[1]);
        __half2 h1 = __floats2half2_rn(p[2], p[3]);
        __half2 h2 = __floats2half2_rn(p[4], p[5]);
        __half2 h3 = __floats2half2_rn(p[6], p[7]);
        uint4 pk = make_uint4(*(uint32_t*)&h0, *(uint32_t*)&h1, *(uint32_t*)&h2, *(uint32_t*)&h3);
        int b = wm * 16 + r;
        long off = ((long)b * NH + h) * EMB + e0 + wn * 64 + j * 16 + c0;
        *(uint4*)(qk + off) = pk;
        __syncwarp();
    }
}

// ---------------- cross_attn: grid (B64, 2); each half does 64 ctx n-tiles ---------
__global__ __launch_bounds__(256) void cross_attn(const __half* __restrict__ qk,
                                                  const __half* __restrict__ ench,
                                                  __half* __restrict__ ctx) {
    int b = blockIdx.x;
    int half = blockIdx.y;
    int tid = threadIdx.x;
    int warp = tid >> 5, lane = tid & 31;
    const __half* A = qk + (long)b * NH * EMB;
    const __half* E = ench + (long)b * TENC * EMB;
    __shared__ float sc[32][72];
    __shared__ __half wsh[32][72];
    __shared__ float patch[8][16][20];

    {
        int wm = warp >> 2, wn = warp & 3;
        wmma::fragment<wmma::accumulator, 16, 16, 16, float> acc;
        wmma::fill_fragment(acc, 0.f);
        for (int k16 = 0; k16 < EMB; k16 += 16) {
            wmma::fragment<wmma::matrix_a, 16, 16, 16, __half, wmma::row_major> a;
            wmma::fragment<wmma::matrix_b, 16, 16, 16, __half, wmma::col_major> bb;
            wmma::load_matrix_sync(a, A + (long)(wm * 16) * EMB + k16, EMB);
            wmma::load_matrix_sync(bb, E + (long)(wn * 16) * EMB + k16, EMB);
            wmma::mma_sync(acc, a, bb, acc);
        }
        wmma::store_matrix_sync(&sc[wm * 16][wn * 16], acc, 72, wmma::mem_row_major);
    }
    __syncthreads();

    if (tid < 32) {
        float mx = -1e30f;
        #pragma unroll
        for (int k = 0; k < TENC; k++) mx = fmaxf(mx, sc[tid][k] * 0.125f);
        float sum = 0.f;
        float ex[TENC];
        #pragma unroll
        for (int k = 0; k < TENC; k++) { ex[k] = expf(sc[tid][k] * 0.125f - mx); sum += ex[k]; }
        float inv = 1.f / sum;
        #pragma unroll
        for (int k = 0; k < TENC; k++) wsh[tid][k] = __float2half(ex[k] * inv);
    }
    __syncthreads();

    {
        int wm = warp >> 2, wn = warp & 3;
        int ntEnd = half * 64 + 64;
        for (int nt = half * 64 + wn; nt < ntEnd; nt += 4) {
            wmma::fragment<wmma::accumulator, 16, 16, 16, float> acc;
            wmma::fill_fragment(acc, 0.f);
            #pragma unroll
            for (int kk = 0; kk < TENC; kk += 16) {
                wmma::fragment<wmma::matrix_a, 16, 16, 16, __half, wmma::row_major> a;
                wmma::fragment<wmma::matrix_b, 16, 16, 16, __half, wmma::row_major> bb;
                wmma::load_matrix_sync(a, &wsh[wm * 16][kk], 72);
                wmma::load_matrix_sync(bb, E + (long)kk * EMB + nt * 16, EMB);
                wmma::mma_sync(acc, a, bb, acc);
            }
            wmma::store_matrix_sync(&patch[warp][0][0], acc, 20, wmma::mem_row_major);
            __syncwarp();
            int r = lane >> 1, c0 = (lane & 1) * 8;
            float* p = &patch[warp][r][c0];
            __half2 h0 = __floats2half2_rn(p[0], p[1]);
            __half2 h1 = __floats2half2_rn(p[2], p[3]);
            __half2 h2 = __floats2half2_rn(p[4], p[5]);
            __half2 h3 = __floats2half2_rn(p[6], p[7]);
            uint4 pk = make_uint4(*(uint32_t*)&h0, *(uint32_t*)&h1, *(uint32_t*)&h2, *(uint32_t*)&h3);
            int h = wm * 16 + r;
            long off = ((long)b * NH + h) * EMB + nt * 16 + c0;
            *(uint4*)(ctx + off) = pk;
            __syncwarp();
        }
    }
}

// ---------------- outv_gemm ----------------
__global__ __launch_bounds__(256) void outv_gemm(const __half* __restrict__ ctx,
                                                 const float* __restrict__ Wv,
                                                 float* __restrict__ part) {
    int h = blockIdx.x, s = blockIdx.y;
    int k0 = s * 512;
    __shared__ __align__(16) __half Bs[32][72];
    int tid = threadIdx.x;
    int warp = tid >> 5;
    int wm = warp >> 1;
    int wn = warp & 1;
    const __half* A = ctx + (long)h * EMB + k0;

    wmma::fragment<wmma::accumulator, 16, 16, 16, float> c[2];
    wmma::fill_fragment(c[0], 0.f);
    wmma::fill_fragment(c[1], 0.f);

    for (int kt = 0; kt < 512; kt += 32) {
        #pragma unroll
        for (int u = 0; u < 2; u++) {
            int idx = tid + u * 256;
            int e = idx >> 4, c4 = (idx & 15) * 4;
            float4 v = *(const float4*)(Wv + (long)(k0 + kt + e) * EMB + h * 64 + c4);
            *(uint2*)&Bs[e][c4] = pack4h(v);
        }
        __syncthreads();
        #pragma unroll
        for (int k16 = 0; k16 < 32; k16 += 16) {
            wmma::fragment<wmma::matrix_a, 16, 16, 16, __half, wmma::row_major> a;
            wmma::load_matrix_sync(a, A + (long)(wm * 16) * (NH * EMB) + kt + k16, NH * EMB);
            #pragma unroll
            for (int j = 0; j < 2; j++) {
                wmma::fragment<wmma::matrix_b, 16, 16, 16, __half, wmma::row_major> bb;
                wmma::load_matrix_sync(bb, &Bs[k16][wn * 32 + j * 16], 72);
                wmma::mma_sync(c[j], a, bb, c[j]);
            }
        }
        __syncthreads();
    }
    float* P = part + (long)(h * 4 + s) * 4096;
    #pragma unroll
    for (int j = 0; j < 2; j++)
        wmma::store_matrix_sync(P + (long)(wm * 16) * 64 + wn * 32 + j * 16,
                                c[j], 64, wmma::mem_row_major);
}

// ---------------- fused epilogues ----------------
template <int NS>
__global__ void reduce_ln_ln(const float* __restrict__ part,
                             const float* __restrict__ g1, const float* __restrict__ b1,
                             const float* __restrict__ res,
                             const float* __restrict__ g2, const float* __restrict__ b2,
                             float* __restrict__ xout, float* __restrict__ yout) {
    const int W = EMB;
    __shared__ float buf[EMB];
    __shared__ float rs[32], rss[32];
    int row = blockIdx.x;
    float s = 0.f, ss = 0.f;
    for (int i = threadIdx.x; i < W; i += blockDim.x) {
        float v = 0.f;
        #pragma unroll
        for (int k = 0; k < NS; k++) v += part[(long)k * B64 * W + (long)row * W + i];
        buf[i] = v; s += v; ss += v * v;
    }
    int wid = threadIdx.x >> 5, lid = threadIdx.x & 31;
    for (int o = 16; o; o >>= 1) { s += __shfl_down_sync(0xffffffffu, s, o); ss += __shfl_down_sync(0xffffffffu, ss, o); }
    if (!lid) { rs[wid] = s; rss[wid] = ss; }
    __syncthreads();
    if (threadIdx.x == 0) {
        float S = 0.f, SS = 0.f;
        for (int i = 0; i < (int)(blockDim.x >> 5); i++) { S += rs[i]; SS += rss[i]; }
        rs[0] = S; rss[0] = SS;
    }
    __syncthreads();
    float m    = rs[0] / (float)W;
    float var  = rss[0] / (float)W - m * m;
    float rstd = rsqrtf(var + 1e-5f);
    __syncthreads();
    float s2 = 0.f, ss2 = 0.f;
    const float* r = res + (long)row * W;
    float* xo = xout + (long)row * W;
    for (int i = threadIdx.x; i < W; i += blockDim.x) {
        float t = r[i] + (buf[i] - m) * rstd * g1[i] + b1[i];
        buf[i] = t; xo[i] = t; s2 += t; ss2 += t * t;
    }
    for (int o = 16; o; o >>= 1) { s2 += __shfl_down_sync(0xffffffffu, s2, o); ss2 += __shfl_down_sync(0xffffffffu, ss2, o); }
    if (!lid) { rs[wid] = s2; rss[wid] = ss2; }
    __syncthreads();
    if (threadIdx.x == 0) {
        float S = 0.f, SS = 0.f;
        for (int i = 0; i < (int)(blockDim.x >> 5); i++) { S += rs[i]; SS += rss[i]; }
        rs[0] = S; rss[0] = SS;
    }
    __syncthreads();
    float m2    = rs[0] / (float)W;
    float var2  = rss[0] / (float)W - m2 * m2;
    float rstd2 = rsqrtf(var2 + 1e-5f);
    float* yo = yout + (long)row * W;
    for (int i = threadIdx.x; i < W; i += blockDim.x)
        yo[i] = (buf[i] - m2) * rstd2 * g2[i] + b2[i];
}

template <int NS>
__global__ void reduce_gelu_ln(const float* __restrict__ part,
                               const float* __restrict__ g, const float* __restrict__ b,
                               float* __restrict__ out) {
    const int W = GDIM;
    __shared__ float buf[GDIM];
    __shared__ float rs[32], rss[32];
    int row = blockIdx.x;
    float s = 0.f, ss = 0.f;
    for (int i = threadIdx.x; i < W; i += blockDim.x) {
        float a = 0.f, c = 0.f;
        #pragma unroll
        for (int k = 0; k < NS; k++) {
            a += part[(long)k * B64 * W + (long)row * W + i];
            c += part[(long)(NS + k) * B64 * W + (long)row * W + i];
        }
        float gl = 0.5f * a * (1.f + erff(a * 0.70710678118654752f));
        float v = gl * c;
        buf[i] = v; s += v; ss += v * v;
    }
    int wid = threadIdx.x >> 5, lid = threadIdx.x & 31;
    for (int o = 16; o; o >>= 1) { s += __shfl_down_sync(0xffffffffu, s, o); ss += __shfl_down_sync(0xffffffffu, ss, o); }
    if (!lid) { rs[wid] = s; rss[wid] = ss; }
    __syncthreads();
    if (threadIdx.x == 0) {
        float S = 0.f, SS = 0.f;
        for (int i = 0; i < (int)(blockDim.x >> 5); i++) { S += rs[i]; SS += rss[i]; }
        rs[0] = S; rss[0] = SS;
    }
    __syncthreads();
    float m    = rs[0] / (float)W;
    float var  = rss[0] / (float)W - m * m;
    float rstd = rsqrtf(var + 1e-5f);
    float* o = out + (long)row * W;
    for (int i = threadIdx.x; i < W; i += blockDim.x)
        o[i] = (buf[i] - m) * rstd * g[i] + b[i];
}

// final: reduce+residual for x; reduce kv partials + token-row scatter
template <int NS>
__global__ void reduce_add_scatter(const float* __restrict__ part, const float* __restrict__ res,
                                   float* __restrict__ out_x, const float* __restrict__ kvpart,
                                   float* __restrict__ outstate, const int* __restrict__ tokp) {
    int idx = blockIdx.x * blockDim.x + threadIdx.x;
    if (idx < B64 * EMB) {
        float s = 0.f;
        #pragma unroll
        for (int k = 0; k < NS; k++) s += part[(long)k * B64 * EMB + idx];
        out_x[idx] = res[idx] + s;
    } else {
        int j = idx - B64 * EMB;
        if (j < 2 * B64 * EMB) {
            int w = j / (B64 * EMB);          // 0 = k, 1 = v
            int rem = j - w * B64 * EMB;
            float s = 0.f;
            #pragma unroll
            for (int k = 0; k < 16; k++) s += kvpart[(long)(w * 16 + k) * B64 * EMB + rem];
            int tok = *tokp;
            int bb = rem >> 11, e = rem & (EMB - 1);
            outstate[((long)((w ? B64 : 0) + bb) * SKV + tok) * EMB + e] = s;
        }
    }
}

// ---------------- self-attention: reduces q/k/v partials in-block ------------------
__global__ __launch_bounds__(256) void self_attn(
    const float* __restrict__ qpart, const float* __restrict__ kvpart,
    const float* __restrict__ astate, float* __restrict__ O,
    const int* __restrict__ tokp) {
    int b = blockIdx.x, h = blockIdx.y;
    int tok = *tokp;
    int L = tok + 1;
    __shared__ float qsh[HC], ksh[HC], vsh[HC];
    __shared__ float sc[SKV];
    __shared__ float red[256];
    __shared__ float vred[4][HC];
    int tid = threadIdx.x;
    if (tid < 192) {
        int w = tid >> 6, cc = tid & 63;
        const float* base = (w == 0)
            ? qpart + (long)b * EMB + h * HC + cc
            : kvpart + (long)((w - 1) * 16) * B64 * EMB + (long)b * EMB + h * HC + cc;
        float s = 0.f;
        #pragma unroll
        for (int k = 0; k < 16; k++) s += base[(long)k * B64 * EMB];
        if (w == 0) qsh[cc] = s;
        else if (w == 1) ksh[cc] = s;
        else vsh[cc] = s;
    }
    __syncthreads();

    int warp = tid >> 5, lane = tid & 31;
    for (int j = warp; j < L; j += 8) {
        float d;
        if (j == tok) {
            d = qsh[lane] * ksh[lane] + qsh[lane + 32] * ksh[lane + 32];
        } else {
            const float* kp = astate + ((long)b * SKV + j) * EMB + h * HC;
            d = qsh[lane] * kp[lane] + qsh[lane + 32] * kp[lane + 32];
        }
        for (int o = 16; o; o >>= 1) d += __shfl_down_sync(0xffffffffu, d, o);
        if (!lane) sc[j] = d * 0.125f;
    }
    __syncthreads();

    float mx = -1e30f;
    for (int j = tid; j < L; j += 256) mx = fmaxf(mx, sc[j]);
    red[tid] = mx; __syncthreads();
    for (int st = 128; st; st >>= 1) { if (tid < st) red[tid] = fmaxf(red[tid], red[tid + st]); __syncthreads(); }
    mx = red[0];
    __syncthreads();

    float sum = 0.f;
    for (int j = tid; j < L; j += 256) { float e = expf(sc[j] - mx); sc[j] = e; sum += e; }
    red[tid] = sum; __syncthreads();
    for (int st = 128; st; st >>= 1) { if (tid < st) red[tid] += red[tid + st]; __syncthreads(); }
    float inv = 1.f / red[0];
    __syncthreads();

    {
        int g = tid >> 6, cc = tid & 63;
        float acc = 0.f;
        const float* vbase = astate + ((long)(B64 + b) * SKV) * EMB + h * HC + cc;
        for (int j = g; j < L; j += 4) {
            float v = (j == tok) ? vsh[cc] : vbase[(long)j * EMB];
            acc += sc[j] * v;
        }
        vred[g][cc] = acc;
    }
    __syncthreads();
    if (tid < HC) {
        float acc = vred[0][tid] + vred[1][tid] + vred[2][tid] + vred[3][tid];
        O[(long)b * EMB + h * HC + tid] = acc * inv;
    }
}

// ---------------- host orchestration ----------------
extern "C" void kernel_launch(void* const* d_in, const int* in_sizes, int n_in,
                              void* d_out, int out_size) {
    const float* dec        = (const float*)d_in[0];
    const float* enc        = (const float*)d_in[1];
    const float* astate     = (const float*)d_in[2];
    const int*   tokp       = (const int*)d_in[4];
    const float* ln_pre_sa_g = (const float*)d_in[5];
    const float* ln_pre_sa_b = (const float*)d_in[6];
    const float* ln_sa_g     = (const float*)d_in[7];
    const float* ln_sa_b     = (const float*)d_in[8];
    const float* ln_pre_ca_g = (const float*)d_in[9];
    const float* ln_pre_ca_b = (const float*)d_in[10];
    const float* ln_ca_g     = (const float*)d_in[11];
    const float* ln_ca_b     = (const float*)d_in[12];
    const float* sa_wq = (const float*)d_in[13];
    const float* sa_wk = (const float*)d_in[14];
    const float* sa_wv = (const float*)d_in[15];
    const float* sa_wo = (const float*)d_in[16];
    const float* ca_wq = (const float*)d_in[17];
    const float* ca_wk = (const float*)d_in[18];
    const float* ca_wv = (const float*)d_in[19];
    const float* ca_wo = (const float*)d_in[20];
    const float* glu_ln0_g = (const float*)d_in[21];
    const float* glu_ln0_b = (const float*)d_in[22];
    const float* glu_fc0   = (const float*)d_in[23];
    const float* glu_fc1   = (const float*)d_in[24];
    const float* glu_ln1_g = (const float*)d_in[25];
    const float* glu_ln1_b = (const float*)d_in[26];
    const float* glu_fc2   = (const float*)d_in[27];

    float* out       = (float*)d_out;
    float* out_x     = out;
    float* out_state = out + (long)B64 * EMB;

    float *x1, *attnout, *x2, *y1, *x3, *z1, *gln, *part, *kvpart, *vpart;
    __half *ench, *qkh, *ctxh;
    cudaGetSymbolAddress((void**)&x1, g_x1);
    cudaGetSymbolAddress((void**)&attnout, g_attnout);
    cudaGetSymbolAddress((void**)&x2, g_x2);
    cudaGetSymbolAddress((void**)&y1, g_y1);
    cudaGetSymbolAddress((void**)&x3, g_x3);
    cudaGetSymbolAddress((void**)&z1, g_z1);
    cudaGetSymbolAddress((void**)&gln, g_gln);
    cudaGetSymbolAddress((void**)&part, g_partial);
    cudaGetSymbolAddress((void**)&kvpart, g_kvpart);
    cudaGetSymbolAddress((void**)&vpart, g_vpart);
    cudaGetSymbolAddress((void**)&ench, g_ench);
    cudaGetSymbolAddress((void**)&qkh, g_qk);
    cudaGetSymbolAddress((void**)&ctxh, g_ctx);

    const float4* stsrc = (const float4*)astate;
    float4* stdst = (float4*)out_state;
    const long N4T = (long)2 * B64 * SKV * EMB / 4;
    const long NE  = (long)B64 * TENC * EMB / 4;
    const long C0 = 2000000, C1 = 4500000, C2 = 7000000, C3 = 9500000, C4 = 14000000;

    // 1. x1 = LN(decoder_state)
    ln_kernel<<<B64, 256>>>(dec, ln_pre_sa_g, ln_pre_sa_b, nullptr, x1, EMB);

    // 2. qkv projections (16 splits; k/v partials -> kvpart) + copy [0,C0) + enc cvt
    wmma_small<<<dim3(EMB / 128, 16, 3 + 2), 256>>>(
        x1, sa_wq, sa_wk, sa_wv, part, EMB, EMB, 3,
        stsrc, stdst, 0, C0, (const float4*)enc, (uint2*)ench, NE, kvpart, nullptr);

    // 3. self-attention (in-block partial reduction; reads astate + partials)
    self_attn<<<dim3(B64, NH), 256>>>(part, kvpart, astate, attnout, tokp);

    // 4. sa out-proj (16 splits) + side copy [C0,C1)
    wmma_small<<<dim3(EMB / 128, 16, 1 + 1), 256>>>(
        attnout, sa_wo, sa_wo, sa_wo, part, EMB, EMB, 1,
        stsrc, stdst, C0, C1, nullptr, nullptr, 0, nullptr, nullptr);
    reduce_ln_ln<16><<<B64, 512>>>(part, ln_sa_g, ln_sa_b, dec, ln_pre_ca_g, ln_pre_ca_b, x2, y1);

    // 5. ca_wq (16 splits) + side copy [C1,C2); qk_gemm reads partials
    wmma_small<<<dim3(EMB / 128, 16, 1 + 1), 256>>>(
        y1, ca_wq, ca_wq, ca_wq, part, EMB, EMB, 1,
        stsrc, stdst, C1, C2, nullptr, nullptr, 0, nullptr, nullptr);
    qk_gemm<16><<<dim3(16, NH), 256>>>(part, ca_wk, qkh);
    cross_attn<<<dim3(B64, 2), 256>>>(qkh, ench, ctxh);
    outv_gemm<<<dim3(NH, 4), 256>>>(ctxh, ca_wv, vpart);

    // 6. ca out-proj (16 splits; A = inline vpart reduction) + side copy [C2,C3)
    wmma_small<<<dim3(EMB / 128, 16, 1 + 1), 256>>>(
        attnout, ca_wo, ca_wo, ca_wo, part, EMB, EMB, 1,
        stsrc, stdst, C2, C3, nullptr, nullptr, 0, nullptr, vpart);
    reduce_ln_ln<16><<<B64, 512>>>(part, ln_ca_g, ln_ca_b, x2, glu_ln0_g, glu_ln0_b, x3, z1);

    // 7. GLU fc0/fc1 (8 splits) + side copy [C3,C4)
    wmma_small<<<dim3(GDIM / 128, 8, 2 + 1), 256>>>(
        z1, glu_fc0, glu_fc1, glu_fc1, part, GDIM, EMB, 2,
        stsrc, stdst, C3, C4, nullptr, nullptr, 0, nullptr, nullptr);
    reduce_gelu_ln<8><<<B64, 512>>>(part, glu_ln1_g, glu_ln1_b, gln);

    // 8. fc2 (16 splits) + side copy [C4,end)
    wmma_small<<<dim3(EMB / 128, 16, 1 + 1), 256>>>(
        gln, glu_fc2, glu_fc2, glu_fc2, part, EMB, GDIM, 1,
        stsrc, stdst, C4, N4T, nullptr, nullptr, 0, nullptr, nullptr);

    // 9. final: residual add + kv-partial reduce + token-row scatter
    reduce_add_scatter<16><<<(3 * B64 * EMB) / 256, 256>>>(part, x3, out_x, kvpart, out_state, tokp);
}

// round 16
// speedup vs baseline: 1.7355x; 1.0497x over previous
#include <cuda_runtime.h>
#include <cuda_fp16.h>
#include <mma.h>
#include <math.h>
#include <stdint.h>

using namespace nvcuda;

#define B64   64
#define EMB   2048
#define GDIM  4096
#define TENC  64
#define SKV   256
#define NH    32
#define HC    64

// ---------------- scratch ----------------
__device__ float g_x1[B64*EMB];
__device__ float g_attnout[B64*EMB];
__device__ float g_x2[B64*EMB];
__device__ float g_y1[B64*EMB];
__device__ float g_x3[B64*EMB];
__device__ float g_z1[B64*EMB];
__device__ float g_gln[B64*GDIM];
__device__ float g_partial[2*8*B64*GDIM];
__device__ float g_kvpart[2*16*B64*EMB];
__device__ float g_vpart[NH*4*HC*B64];
__device__ __half g_ench[B64*TENC*EMB];
__device__ __half g_qk[B64*NH*EMB];
__device__ __half g_ctx[B64*NH*EMB];

__device__ __forceinline__ uint2 pack4h(float4 v) {
    __half2 h0 = __floats2half2_rn(v.x, v.y);
    __half2 h1 = __floats2half2_rn(v.z, v.w);
    uint2 u;
    u.x = *(uint32_t*)&h0;
    u.y = *(uint32_t*)&h1;
    return u;
}

__device__ __forceinline__ void side_copy(const float4* __restrict__ src,
                                          float4* __restrict__ dst,
                                          long cb, long ce, long sid, long nb) {
    long stride = nb * 256;
    for (long i = cb + sid * 256 + threadIdx.x; i < ce; i += stride)
        dst[i] = src[i];
}

// ---------------- layernorm ----------------
__global__ void ln_kernel(const float* __restrict__ in, const float* __restrict__ g,
                          const float* __restrict__ b, const float* __restrict__ res,
                          float* __restrict__ out, int W) {
    int row = blockIdx.x;
    const float* x = in + (long)row * W;
    float s = 0.f, ss = 0.f;
    for (int i = threadIdx.x; i < W; i += blockDim.x) { float v = x[i]; s += v; ss += v * v; }
    __shared__ float rs[32], rss[32];
    for (int o = 16; o; o >>= 1) { s += __shfl_down_sync(0xffffffffu, s, o); ss += __shfl_down_sync(0xffffffffu, ss, o); }
    int wid = threadIdx.x >> 5, lid = threadIdx.x & 31;
    if (!lid) { rs[wid] = s; rss[wid] = ss; }
    __syncthreads();
    if (threadIdx.x == 0) {
        float S = 0.f, SS = 0.f;
        int nw = blockDim.x >> 5;
        for (int i = 0; i < nw; i++) { S += rs[i]; SS += rss[i]; }
        rs[0] = S; rss[0] = SS;
    }
    __syncthreads();
    float m    = rs[0] / (float)W;
    float var  = rss[0] / (float)W - m * m;
    float rstd = rsqrtf(var + 1e-5f);
    float* o = out + (long)row * W;
    const float* r = res ? res + (long)row * W : nullptr;
    for (int i = threadIdx.x; i < W; i += blockDim.x) {
        float v = (x[i] - m) * rstd * g[i] + b[i];
        o[i] = r ? (r[i] + v) : v;
    }
}

// ---------------- small GEMM with side-work planes ----------------
__global__ __launch_bounds__(256) void wmma_small(
    const float* __restrict__ A, const float* __restrict__ Wa,
    const float* __restrict__ Wb, const float* __restrict__ Wc,
    float* __restrict__ part, int N, int K, int nW,
    const float4* __restrict__ csrc, float4* __restrict__ cdst, long cb, long ce,
    const float4* __restrict__ vsrc, uint2* __restrict__ vdst, long vn,
    float* __restrict__ partKV, const float* __restrict__ vp) {
    int zw = blockIdx.z;
    if (zw >= nW) {
        int role = zw - nW;
        long nb = (long)gridDim.x * gridDim.y;
        long sid = (long)blockIdx.y * gridDim.x + blockIdx.x;
        if (role == 0) {
            side_copy(csrc, cdst, cb, ce, sid, nb);
        } else {
            long stride = nb * 256;
            for (long i = sid * 256 + threadIdx.x; i < vn; i += stride)
                vdst[i] = pack4h(vsrc[i]);
        }
        return;
    }
    int nt = blockIdx.x, s = blockIdx.y, w = zw;
    int nS = gridDim.y;
    const float* W = (w == 0) ? Wa : ((w == 1) ? Wb : Wc);
    int Ks = K / nS;
    int k0 = s * Ks;
    int n0 = nt * 128;
    __shared__ __align__(16) __half As[2][64][40];
    __shared__ __align__(16) __half Bs[2][32][136];
    int tid = threadIdx.x;
    int warp = tid >> 5;
    int wm = warp >> 1;
    int wn = warp & 1;

    wmma::fragment<wmma::accumulator, 16, 16, 16, float> c[4];
    #pragma unroll
    for (int j = 0; j < 4; j++) wmma::fill_fragment(c[j], 0.f);

    float4 ra[2], rb[4];
    int ar[2], ac[2], br[4], bc[4];
    #pragma unroll
    for (int u = 0; u < 2; u++) {
        int idx = tid + u * 256;
        ar[u] = idx >> 3;  ac[u] = (idx & 7) * 4;
    }
    #pragma unroll
    for (int u = 0; u < 4; u++) {
        int idx = tid + u * 256;
        br[u] = idx >> 5;  bc[u] = (idx & 31) * 4;
    }
    auto loadG = [&](int kt) {
        if (vp) {
            #pragma unroll
            for (int u = 0; u < 2; u++) {
                int e = k0 + kt + ac[u];
                int hh = e >> 6, cc = e & 63;
                float4 acc = make_float4(0.f, 0.f, 0.f, 0.f);
                #pragma unroll
                for (int sv = 0; sv < 4; sv++) {
                    float4 v = *(const float4*)(vp + (long)(hh * 4 + sv) * 4096 + ar[u] * 64 + cc);
                    acc.x += v.x; acc.y += v.y; acc.z += v.z; acc.w += v.w;
                }
                ra[u] = acc;
            }
        } else {
            #pragma unroll
            for (int u = 0; u < 2; u++)
                ra[u] = *(const float4*)(A + (long)ar[u] * K + k0 + kt + ac[u]);
        }
        #pragma unroll
        for (int u = 0; u < 4; u++)
            rb[u] = *(const float4*)(W + (long)(k0 + kt + br[u]) * N + n0 + bc[u]);
    };
    auto storeS = [&](int buf) {
        #pragma unroll
        for (int u = 0; u < 2; u++)
            *(uint2*)&As[buf][ar[u]][ac[u]] = pack4h(ra[u]);
        #pragma unroll
        for (int u = 0; u < 4; u++)
            *(uint2*)&Bs[buf][br[u]][bc[u]] = pack4h(rb[u]);
    };

    loadG(0);
    storeS(0);
    __syncthreads();
    int buf = 0;

    for (int kt = 0; kt < Ks; kt += 32) {
        int nxt = kt + 32;
        if (nxt < Ks) loadG(nxt);
        #pragma unroll
        for (int k16 = 0; k16 < 32; k16 += 16) {
            wmma::fragment<wmma::matrix_a, 16, 16, 16, __half, wmma::row_major> a;
            wmma::load_matrix_sync(a, &As[buf][wm * 16][k16], 40);
            #pragma unroll
            for (int j = 0; j < 4; j++) {
                wmma::fragment<wmma::matrix_b, 16, 16, 16, __half, wmma::row_major> b;
                wmma::load_matrix_sync(b, &Bs[buf][k16][wn * 64 + j * 16], 136);
                wmma::mma_sync(c[j], a, b, c[j]);
            }
        }
        if (nxt < Ks) storeS(buf ^ 1);
        __syncthreads();
        buf ^= 1;
    }
    float* P = (partKV && w >= 1)
        ? partKV + (long)((w - 1) * nS + s) * 64 * N
        : part + (long)(w * nS + s) * 64 * N;
    #pragma unroll
    for (int j = 0; j < 4; j++)
        wmma::store_matrix_sync(P + (long)(wm * 16) * N + n0 + wn * 64 + j * 16,
                                c[j], N, wmma::mem_row_major);
}

// ---------------- qk_gemm ----------------
template <int NS>
__global__ __launch_bounds__(256) void qk_gemm(const float* __restrict__ part,
                                               const float* __restrict__ Wk,
                                               __half* __restrict__ qk) {
    int e0 = blockIdx.x * 128, h = blockIdx.y;
    __shared__ __align__(16) __half As[64][72];
    __shared__ __align__(16) __half Bs[128][72];
    __shared__ float patch[8][16][20];
    int tid = threadIdx.x;
    int warp = tid >> 5, lane = tid & 31;
    int wm = warp >> 1;
    int wn = warp & 1;

    #pragma unroll
    for (int u = 0; u < 4; u++) {
        int idx = tid + u * 256;
        int b = idx >> 4, c4 = (idx & 15) * 4;
        float4 acc = make_float4(0.f, 0.f, 0.f, 0.f);
        #pragma unroll
        for (int k = 0; k < NS; k++) {
            float4 v = *(const float4*)(part + (long)k * B64 * EMB + (long)b * EMB + h * 64 + c4);
            acc.x += v.x; acc.y += v.y; acc.z += v.z; acc.w += v.w;
        }
        *(uint2*)&As[b][c4] = pack4h(acc);
    }
    #pragma unroll
    for (int u = 0; u < 8; u++) {
        int idx = tid + u * 256;
        int e = idx >> 4, c4 = (idx & 15) * 4;
        float4 v = *(const float4*)(Wk + (long)(e0 + e) * EMB + h * 64 + c4);
        *(uint2*)&Bs[e][c4] = pack4h(v);
    }
    __syncthreads();

    wmma::fragment<wmma::accumulator, 16, 16, 16, float> c[4];
    #pragma unroll
    for (int j = 0; j < 4; j++) wmma::fill_fragment(c[j], 0.f);
    #pragma unroll
    for (int k16 = 0; k16 < 64; k16 += 16) {
        wmma::fragment<wmma::matrix_a, 16, 16, 16, __half, wmma::row_major> a;
        wmma::load_matrix_sync(a, &As[wm * 16][k16], 72);
        #pragma unroll
        for (int j = 0; j < 4; j++) {
            wmma::fragment<wmma::matrix_b, 16, 16, 16, __half, wmma::col_major> b;
            wmma::load_matrix_sync(b, &Bs[wn * 64 + j * 16][k16], 72);
            wmma::mma_sync(c[j], a, b, c[j]);
        }
    }
    #pragma unroll
    for (int j = 0; j < 4; j++) {
        wmma::store_matrix_sync(&patch[warp][0][0], c[j], 20, wmma::mem_row_major);
        __syncwarp();
        int r = lane >> 1, c0 = (lane & 1) * 8;
        float* p = &patch[warp][r][c0];
        __half2 h0 = __floats2half2_rn(p[0], p[1]);
        __half2 h1 = __floats2half2_rn(p[2], p[3]);
        __half2 h2 = __floats2half2_rn(p[4], p[5]);
        __half2 h3 = __floats2half2_rn(p[6], p[7]);
        uint4 pk = make_uint4(*(uint32_t*)&h0, *(uint32_t*)&h1, *(uint32_t*)&h2, *(uint32_t*)&h3);
        int b = wm * 16 + r;
        long off = ((long)b * NH + h) * EMB + e0 + wn * 64 + j * 16 + c0;
        *(uint4*)(qk + off) = pk;
        __syncwarp();
    }
}

// ---------------- cross_attn ----------------
__global__ __launch_bounds__(256) void cross_attn(const __half* __restrict__ qk,
                                                  const __half* __restrict__ ench,
                                                  __half* __restrict__ ctx) {
    int b = blockIdx.x;
    int half = blockIdx.y;
    int tid = threadIdx.x;
    int warp = tid >> 5, lane = tid & 31;
    const __half* A = qk + (long)b * NH * EMB;
    const __half* E = ench + (long)b * TENC * EMB;
    __shared__ float sc[32][72];
    __shared__ __half wsh[32][72];
    __shared__ float patch[8][16][20];

    {
        int wm = warp >> 2, wn = warp & 3;
        wmma::fragment<wmma::accumulator, 16, 16, 16, float> acc;
        wmma::fill_fragment(acc, 0.f);
        for (int k16 = 0; k16 < EMB; k16 += 16) {
            wmma::fragment<wmma::matrix_a, 16, 16, 16, __half, wmma::row_major> a;
            wmma::fragment<wmma::matrix_b, 16, 16, 16, __half, wmma::col_major> bb;
            wmma::load_matrix_sync(a, A + (long)(wm * 16) * EMB + k16, EMB);
            wmma::load_matrix_sync(bb, E + (long)(wn * 16) * EMB + k16, EMB);
            wmma::mma_sync(acc, a, bb, acc);
        }
        wmma::store_matrix_sync(&sc[wm * 16][wn * 16], acc, 72, wmma::mem_row_major);
    }
    __syncthreads();

    if (tid < 32) {
        float mx = -1e30f;
        #pragma unroll
        for (int k = 0; k < TENC; k++) mx = fmaxf(mx, sc[tid][k] * 0.125f);
        float sum = 0.f;
        float ex[TENC];
        #pragma unroll
        for (int k = 0; k < TENC; k++) { ex[k] = expf(sc[tid][k] * 0.125f - mx); sum += ex[k]; }
        float inv = 1.f / sum;
        #pragma unroll
        for (int k = 0; k < TENC; k++) wsh[tid][k] = __float2half(ex[k] * inv);
    }
    __syncthreads();

    {
        int wm = warp >> 2, wn = warp & 3;
        int ntEnd = half * 64 + 64;
        for (int nt = half * 64 + wn; nt < ntEnd; nt += 4) {
            wmma::fragment<wmma::accumulator, 16, 16, 16, float> acc;
            wmma::fill_fragment(acc, 0.f);
            #pragma unroll
            for (int kk = 0; kk < TENC; kk += 16) {
                wmma::fragment<wmma::matrix_a, 16, 16, 16, __half, wmma::row_major> a;
                wmma::fragment<wmma::matrix_b, 16, 16, 16, __half, wmma::row_major> bb;
                wmma::load_matrix_sync(a, &wsh[wm * 16][kk], 72);
                wmma::load_matrix_sync(bb, E + (long)kk * EMB + nt * 16, EMB);
                wmma::mma_sync(acc, a, bb, acc);
            }
            wmma::store_matrix_sync(&patch[warp][0][0], acc, 20, wmma::mem_row_major);
            __syncwarp();
            int r = lane >> 1, c0 = (lane & 1) * 8;
            float* p = &patch[warp][r][c0];
            __half2 h0 = __floats2half2_rn(p[0], p[1]);
            __half2 h1 = __floats2half2_rn(p[2], p[3]);
            __half2 h2 = __floats2half2_rn(p[4], p[5]);
            __half2 h3 = __floats2half2_rn(p[6], p[7]);
            uint4 pk = make_uint4(*(uint32_t*)&h0, *(uint32_t*)&h1, *(uint32_t*)&h2, *(uint32_t*)&h3);
            int h = wm * 16 + r;
            long off = ((long)b * NH + h) * EMB + nt * 16 + c0;
            *(uint4*)(ctx + off) = pk;
            __syncwarp();
        }
    }
}

// ---------------- outv_gemm ----------------
__global__ __launch_bounds__(256) void outv_gemm(const __half* __restrict__ ctx,
                                                 const float* __restrict__ Wv,
                                                 float* __restrict__ part) {
    int h = blockIdx.x, s = blockIdx.y;
    int k0 = s * 512;
    __shared__ __align__(16) __half Bs[32][72];
    int tid = threadIdx.x;
    int warp = tid >> 5;
    int wm = warp >> 1;
    int wn = warp & 1;
    const __half* A = ctx + (long)h * EMB + k0;

    wmma::fragment<wmma::accumulator, 16, 16, 16, float> c[2];
    wmma::fill_fragment(c[0], 0.f);
    wmma::fill_fragment(c[1], 0.f);

    for (int kt = 0; kt < 512; kt += 32) {
        #pragma unroll
        for (int u = 0; u < 2; u++) {
            int idx = tid + u * 256;
            int e = idx >> 4, c4 = (idx & 15) * 4;
            float4 v = *(const float4*)(Wv + (long)(k0 + kt + e) * EMB + h * 64 + c4);
            *(uint2*)&Bs[e][c4] = pack4h(v);
        }
        __syncthreads();
        #pragma unroll
        for (int k16 = 0; k16 < 32; k16 += 16) {
            wmma::fragment<wmma::matrix_a, 16, 16, 16, __half, wmma::row_major> a;
            wmma::load_matrix_sync(a, A + (long)(wm * 16) * (NH * EMB) + kt + k16, NH * EMB);
            #pragma unroll
            for (int j = 0; j < 2; j++) {
                wmma::fragment<wmma::matrix_b, 16, 16, 16, __half, wmma::row_major> bb;
                wmma::load_matrix_sync(bb, &Bs[k16][wn * 32 + j * 16], 72);
                wmma::mma_sync(c[j], a, bb, c[j]);
            }
        }
        __syncthreads();
    }
    float* P = part + (long)(h * 4 + s) * 4096;
    #pragma unroll
    for (int j = 0; j < 2; j++)
        wmma::store_matrix_sync(P + (long)(wm * 16) * 64 + wn * 32 + j * 16,
                                c[j], 64, wmma::mem_row_major);
}

// ---------------- fused epilogues (with copy side-blocks) ----------------
template <int NS>
__global__ void reduce_ln_ln(const float* __restrict__ part,
                             const float* __restrict__ g1, const float* __restrict__ b1,
                             const float* __restrict__ res,
                             const float* __restrict__ g2, const float* __restrict__ b2,
                             float* __restrict__ xout, float* __restrict__ yout,
                             const float4* __restrict__ csrc, float4* __restrict__ cdst,
                             long cb, long ce) {
    if (blockIdx.x >= B64) {
        long nb = gridDim.x - B64;
        long sid = blockIdx.x - B64;
        long stride = nb * blockDim.x;
        for (long i = cb + sid * blockDim.x + threadIdx.x; i < ce; i += stride)
            cdst[i] = csrc[i];
        return;
    }
    const int W = EMB;
    __shared__ float buf[EMB];
    __shared__ float rs[32], rss[32];
    int row = blockIdx.x;
    float s = 0.f, ss = 0.f;
    for (int i = threadIdx.x; i < W; i += blockDim.x) {
        float v = 0.f;
        #pragma unroll
        for (int k = 0; k < NS; k++) v += part[(long)k * B64 * W + (long)row * W + i];
        buf[i] = v; s += v; ss += v * v;
    }
    int wid = threadIdx.x >> 5, lid = threadIdx.x & 31;
    for (int o = 16; o; o >>= 1) { s += __shfl_down_sync(0xffffffffu, s, o); ss += __shfl_down_sync(0xffffffffu, ss, o); }
    if (!lid) { rs[wid] = s; rss[wid] = ss; }
    __syncthreads();
    if (threadIdx.x == 0) {
        float S = 0.f, SS = 0.f;
        for (int i = 0; i < (int)(blockDim.x >> 5); i++) { S += rs[i]; SS += rss[i]; }
        rs[0] = S; rss[0] = SS;
    }
    __syncthreads();
    float m    = rs[0] / (float)W;
    float var  = rss[0] / (float)W - m * m;
    float rstd = rsqrtf(var + 1e-5f);
    __syncthreads();
    float s2 = 0.f, ss2 = 0.f;
    const float* r = res + (long)row * W;
    float* xo = xout + (long)row * W;
    for (int i = threadIdx.x; i < W; i += blockDim.x) {
        float t = r[i] + (buf[i] - m) * rstd * g1[i] + b1[i];
        buf[i] = t; xo[i] = t; s2 += t; ss2 += t * t;
    }
    for (int o = 16; o; o >>= 1) { s2 += __shfl_down_sync(0xffffffffu, s2, o); ss2 += __shfl_down_sync(0xffffffffu, ss2, o); }
    if (!lid) { rs[wid] = s2; rss[wid] = ss2; }
    __syncthreads();
    if (threadIdx.x == 0) {
        float S = 0.f, SS = 0.f;
        for (int i = 0; i < (int)(blockDim.x >> 5); i++) { S += rs[i]; SS += rss[i]; }
        rs[0] = S; rss[0] = SS;
    }
    __syncthreads();
    float m2    = rs[0] / (float)W;
    float var2  = rss[0] / (float)W - m2 * m2;
    float rstd2 = rsqrtf(var2 + 1e-5f);
    float* yo = yout + (long)row * W;
    for (int i = threadIdx.x; i < W; i += blockDim.x)
        yo[i] = (buf[i] - m2) * rstd2 * g2[i] + b2[i];
}

template <int NS>
__global__ void reduce_gelu_ln(const float* __restrict__ part,
                               const float* __restrict__ g, const float* __restrict__ b,
                               float* __restrict__ out,
                               const float4* __restrict__ csrc, float4* __restrict__ cdst,
                               long cb, long ce) {
    if (blockIdx.x >= B64) {
        long nb = gridDim.x - B64;
        long sid = blockIdx.x - B64;
        long stride = nb * blockDim.x;
        for (long i = cb + sid * blockDim.x + threadIdx.x; i < ce; i += stride)
            cdst[i] = csrc[i];
        return;
    }
    const int W = GDIM;
    __shared__ float buf[GDIM];
    __shared__ float rs[32], rss[32];
    int row = blockIdx.x;
    float s = 0.f, ss = 0.f;
    for (int i = threadIdx.x; i < W; i += blockDim.x) {
        float a = 0.f, c = 0.f;
        #pragma unroll
        for (int k = 0; k < NS; k++) {
            a += part[(long)k * B64 * W + (long)row * W + i];
            c += part[(long)(NS + k) * B64 * W + (long)row * W + i];
        }
        float gl = 0.5f * a * (1.f + erff(a * 0.70710678118654752f));
        float v = gl * c;
        buf[i] = v; s += v; ss += v * v;
    }
    int wid = threadIdx.x >> 5, lid = threadIdx.x & 31;
    for (int o = 16; o; o >>= 1) { s += __shfl_down_sync(0xffffffffu, s, o); ss += __shfl_down_sync(0xffffffffu, ss, o); }
    if (!lid) { rs[wid] = s; rss[wid] = ss; }
    __syncthreads();
    if (threadIdx.x == 0) {
        float S = 0.f, SS = 0.f;
        for (int i = 0; i < (int)(blockDim.x >> 5); i++) { S += rs[i]; SS += rss[i]; }
        rs[0] = S; rss[0] = SS;
    }
    __syncthreads();
    float m    = rs[0] / (float)W;
    float var  = rss[0] / (float)W - m * m;
    float rstd = rsqrtf(var + 1e-5f);
    float* o = out + (long)row * W;
    for (int i = threadIdx.x; i < W; i += blockDim.x)
        o[i] = (buf[i] - m) * rstd * g[i] + b[i];
}

template <int NS>
__global__ void reduce_add_scatter(const float* __restrict__ part, const float* __restrict__ res,
                                   float* __restrict__ out_x, const float* __restrict__ kvpart,
                                   float* __restrict__ outstate, const int* __restrict__ tokp) {
    int idx = blockIdx.x * blockDim.x + threadIdx.x;
    if (idx < B64 * EMB) {
        float s = 0.f;
        #pragma unroll
        for (int k = 0; k < NS; k++) s += part[(long)k * B64 * EMB + idx];
        out_x[idx] = res[idx] + s;
    } else {
        int j = idx - B64 * EMB;
        if (j < 2 * B64 * EMB) {
            int w = j / (B64 * EMB);
            int rem = j - w * B64 * EMB;
            float s = 0.f;
            #pragma unroll
            for (int k = 0; k < 16; k++) s += kvpart[(long)(w * 16 + k) * B64 * EMB + rem];
            int tok = *tokp;
            int bb = rem >> 11, e = rem & (EMB - 1);
            outstate[((long)((w ? B64 : 0) + bb) * SKV + tok) * EMB + e] = s;
        }
    }
}

// ---------------- self-attention (z==1 plane: state copy) ----------------
__global__ __launch_bounds__(256) void self_attn(
    const float* __restrict__ qpart, const float* __restrict__ kvpart,
    const float* __restrict__ astate, float* __restrict__ O,
    const int* __restrict__ tokp,
    const float4* __restrict__ csrc, float4* __restrict__ cdst, long cb, long ce) {
    if (blockIdx.z == 1) {
        long nb = (long)gridDim.x * gridDim.y;
        long sid = (long)blockIdx.y * gridDim.x + blockIdx.x;
        side_copy(csrc, cdst, cb, ce, sid, nb);
        return;
    }
    int b = blockIdx.x, h = blockIdx.y;
    int tok = *tokp;
    int L = tok + 1;
    __shared__ float qsh[HC], ksh[HC], vsh[HC];
    __shared__ float sc[SKV];
    __shared__ float red[256];
    __shared__ float vred[4][HC];
    int tid = threadIdx.x;
    if (tid < 192) {
        int w = tid >> 6, cc = tid & 63;
        const float* base = (w == 0)
            ? qpart + (long)b * EMB + h * HC + cc
            : kvpart + (long)((w - 1) * 16) * B64 * EMB + (long)b * EMB + h * HC + cc;
        float s = 0.f;
        #pragma unroll
        for (int k = 0; k < 16; k++) s += base[(long)k * B64 * EMB];
        if (w == 0) qsh[cc] = s;
        else if (w == 1) ksh[cc] = s;
        else vsh[cc] = s;
    }
    __syncthreads();

    int warp = tid >> 5, lane = tid & 31;
    for (int j = warp; j < L; j += 8) {
        float d;
        if (j == tok) {
            d = qsh[lane] * ksh[lane] + qsh[lane + 32] * ksh[lane + 32];
        } else {
            const float* kp = astate + ((long)b * SKV + j) * EMB + h * HC;
            d = qsh[lane] * kp[lane] + qsh[lane + 32] * kp[lane + 32];
        }
        for (int o = 16; o; o >>= 1) d += __shfl_down_sync(0xffffffffu, d, o);
        if (!lane) sc[j] = d * 0.125f;
    }
    __syncthreads();

    float mx = -1e30f;
    for (int j = tid; j < L; j += 256) mx = fmaxf(mx, sc[j]);
    red[tid] = mx; __syncthreads();
    for (int st = 128; st; st >>= 1) { if (tid < st) red[tid] = fmaxf(red[tid], red[tid + st]); __syncthreads(); }
    mx = red[0];
    __syncthreads();

    float sum = 0.f;
    for (int j = tid; j < L; j += 256) { float e = expf(sc[j] - mx); sc[j] = e; sum += e; }
    red[tid] = sum; __syncthreads();
    for (int st = 128; st; st >>= 1) { if (tid < st) red[tid] += red[tid + st]; __syncthreads(); }
    float inv = 1.f / red[0];
    __syncthreads();

    {
        int g = tid >> 6, cc = tid & 63;
        float acc = 0.f;
        const float* vbase = astate + ((long)(B64 + b) * SKV) * EMB + h * HC + cc;
        for (int j = g; j < L; j += 4) {
            float v = (j == tok) ? vsh[cc] : vbase[(long)j * EMB];
            acc += sc[j] * v;
        }
        vred[g][cc] = acc;
    }
    __syncthreads();
    if (tid < HC) {
        float acc = vred[0][tid] + vred[1][tid] + vred[2][tid] + vred[3][tid];
        O[(long)b * EMB + h * HC + tid] = acc * inv;
    }
}

// ---------------- host orchestration ----------------
extern "C" void kernel_launch(void* const* d_in, const int* in_sizes, int n_in,
                              void* d_out, int out_size) {
    const float* dec        = (const float*)d_in[0];
    const float* enc        = (const float*)d_in[1];
    const float* astate     = (const float*)d_in[2];
    const int*   tokp       = (const int*)d_in[4];
    const float* ln_pre_sa_g = (const float*)d_in[5];
    const float* ln_pre_sa_b = (const float*)d_in[6];
    const float* ln_sa_g     = (const float*)d_in[7];
    const float* ln_sa_b     = (const float*)d_in[8];
    const float* ln_pre_ca_g = (const float*)d_in[9];
    const float* ln_pre_ca_b = (const float*)d_in[10];
    const float* ln_ca_g     = (const float*)d_in[11];
    const float* ln_ca_b     = (const float*)d_in[12];
    const float* sa_wq = (const float*)d_in[13];
    const float* sa_wk = (const float*)d_in[14];
    const float* sa_wv = (const float*)d_in[15];
    const float* sa_wo = (const float*)d_in[16];
    const float* ca_wq = (const float*)d_in[17];
    const float* ca_wk = (const float*)d_in[18];
    const float* ca_wv = (const float*)d_in[19];
    const float* ca_wo = (const float*)d_in[20];
    const float* glu_ln0_g = (const float*)d_in[21];
    const float* glu_ln0_b = (const float*)d_in[22];
    const float* glu_fc0   = (const float*)d_in[23];
    const float* glu_fc1   = (const float*)d_in[24];
    const float* glu_ln1_g = (const float*)d_in[25];
    const float* glu_ln1_b = (const float*)d_in[26];
    const float* glu_fc2   = (const float*)d_in[27];

    float* out       = (float*)d_out;
    float* out_x     = out;
    float* out_state = out + (long)B64 * EMB;

    float *x1, *attnout, *x2, *y1, *x3, *z1, *gln, *part, *kvpart, *vpart;
    __half *ench, *qkh, *ctxh;
    cudaGetSymbolAddress((void**)&x1, g_x1);
    cudaGetSymbolAddress((void**)&attnout, g_attnout);
    cudaGetSymbolAddress((void**)&x2, g_x2);
    cudaGetSymbolAddress((void**)&y1, g_y1);
    cudaGetSymbolAddress((void**)&x3, g_x3);
    cudaGetSymbolAddress((void**)&z1, g_z1);
    cudaGetSymbolAddress((void**)&gln, g_gln);
    cudaGetSymbolAddress((void**)&part, g_partial);
    cudaGetSymbolAddress((void**)&kvpart, g_kvpart);
    cudaGetSymbolAddress((void**)&vpart, g_vpart);
    cudaGetSymbolAddress((void**)&ench, g_ench);
    cudaGetSymbolAddress((void**)&qkh, g_qk);
    cudaGetSymbolAddress((void**)&ctxh, g_ctx);

    const float4* stsrc = (const float4*)astate;
    float4* stdst = (float4*)out_state;
    const long N4T = (long)2 * B64 * SKV * EMB / 4;   // 16,777,216
    const long NE  = (long)B64 * TENC * EMB / 4;
    // chunk boundaries across 10 carrier launches
    const long D0 = 2000000;    // qkv
    const long D1 = 5000000;    // self_attn
    const long D2 = 6800000;    // sa_wo
    const long D3 = 8000000;    // reduce_ln_ln #1
    const long D4 = 9800000;    // ca_wq
    const long D5 = 11600000;   // ca_wo
    const long D6 = 12800000;   // reduce_ln_ln #2
    const long D7 = 15100000;   // fc0/fc1
    const long D8 = 15800000;   // reduce_gelu_ln

    // 1. x1 = LN(decoder_state)
    ln_kernel<<<B64, 256>>>(dec, ln_pre_sa_g, ln_pre_sa_b, nullptr, x1, EMB);

    // 2. qkv projections + copy [0,D0) + enc cvt
    wmma_small<<<dim3(EMB / 128, 16, 3 + 2), 256>>>(
        x1, sa_wq, sa_wk, sa_wv, part, EMB, EMB, 3,
        stsrc, stdst, 0, D0, (const float4*)enc, (uint2*)ench, NE, kvpart, nullptr);

    // 3. self-attention + copy [D0,D1)
    self_attn<<<dim3(B64, NH, 2), 256>>>(part, kvpart, astate, attnout, tokp,
                                         stsrc, stdst, D0, D1);

    // 4. sa out-proj + copy [D1,D2)
    wmma_small<<<dim3(EMB / 128, 16, 1 + 1), 256>>>(
        attnout, sa_wo, sa_wo, sa_wo, part, EMB, EMB, 1,
        stsrc, stdst, D1, D2, nullptr, nullptr, 0, nullptr, nullptr);
    reduce_ln_ln<16><<<B64 + 96, 512>>>(part, ln_sa_g, ln_sa_b, dec,
                                        ln_pre_ca_g, ln_pre_ca_b, x2, y1,
                                        stsrc, stdst, D2, D3);

    // 5. ca_wq + copy [D3,D4); qk_gemm reads partials
    wmma_small<<<dim3(EMB / 128, 16, 1 + 1), 256>>>(
        y1, ca_wq, ca_wq, ca_wq, part, EMB, EMB, 1,
        stsrc, stdst, D3, D4, nullptr, nullptr, 0, nullptr, nullptr);
    qk_gemm<16><<<dim3(16, NH), 256>>>(part, ca_wk, qkh);
    cross_attn<<<dim3(B64, 2), 256>>>(qkh, ench, ctxh);
    outv_gemm<<<dim3(NH, 4), 256>>>(ctxh, ca_wv, vpart);

    // 6. ca out-proj (A = inline vpart reduction) + copy [D4,D5)
    wmma_small<<<dim3(EMB / 128, 16, 1 + 1), 256>>>(
        attnout, ca_wo, ca_wo, ca_wo, part, EMB, EMB, 1,
        stsrc, stdst, D4, D5, nullptr, nullptr, 0, nullptr, vpart);
    reduce_ln_ln<16><<<B64 + 96, 512>>>(part, ln_ca_g, ln_ca_b, x2,
                                        glu_ln0_g, glu_ln0_b, x3, z1,
                                        stsrc, stdst, D5, D6);

    // 7. GLU fc0/fc1 + copy [D6,D7)
    wmma_small<<<dim3(GDIM / 128, 8, 2 + 1), 256>>>(
        z1, glu_fc0, glu_fc1, glu_fc1, part, GDIM, EMB, 2,
        stsrc, stdst, D6, D7, nullptr, nullptr, 0, nullptr, nullptr);
    reduce_gelu_ln<8><<<B64 + 96, 512>>>(part, glu_ln1_g, glu_ln1_b, gln,
                                         stsrc, stdst, D7, D8);

    // 8. fc2 + copy [D8,end)
    wmma_small<<<dim3(EMB / 128, 16, 1 + 1), 256>>>(
        gln, glu_fc2, glu_fc2, glu_fc2, part, EMB, GDIM, 1,
        stsrc, stdst, D8, N4T, nullptr, nullptr, 0, nullptr, nullptr);

    // 9. final: residual add + kv-partial reduce + token-row scatter
    reduce_add_scatter<16><<<(3 * B64 * EMB) / 256, 256>>>(part, x3, out_x, kvpart, out_state, tokp);
}